// round 10
// baseline (speedup 1.0000x reference)
#include <cuda_runtime.h>
#include <cuda_bf16.h>
#include <math.h>

// Problem constants
#define B_    16
#define T_    64
#define H_    1024
#define D_    2048      // 2H
#define EMB_  512
#define MO_   1024      // maxout units
#define V_    32000
#define G3_   3072      // 3H
#define CAT_  3584      // H + EMB + D
#define NBLK  148       // persistent grid (<= SM count => co-resident)

// Dynamic smem layout for recur_kernel (bytes)
#define WPITCH     24
#define WHH_BYTES2 (1024 * WPITCH * 4)       // 98304  (W_hh cols, tf32)
#define HSPITCH    1026                      // bank-padded Hih row (floats)
#define HS_OFF2    WHH_BYTES2                // 98304
#define RED_OFF    (HS_OFF2 + 86208)         // 184512 (16 x 16 x 28 reduce)
#define GI_OFF     (RED_OFF + 28672)         // 213184 (16 x 24 gi)
#define E_OFF2     (GI_OFF + 1536)           // 214720 (16 x 65 e)
#define DSMEM2     (E_OFF2 + 4160)           // 218880

// Dynamic smem for the 256x128 GEMM (bytes)
#define G2_AS_BYTES (2 * 256 * 20 * 4)       // 40960
#define G2_BS_BYTES (2 * 16 * 136 * 4)       // 17408
#define G2_SMEM     (G2_AS_BYTES + G2_BS_BYTES)  // 58368

// ---------------- scratch (device globals) ----------------------------------
__device__ float g_hemb[B_ * T_ * T_];          // h @ W_h + b_h      [b*T+t][j]
__device__ float g_Hih [B_ * T_ * G3_];         // h @ W_ih + b_ih
__device__ float g_s   [B_ * H_];               // GRU state
__device__ float g_E   [T_ * B_ * T_];          // attention weights [i][b][t]
__device__ float g_gpart[16 * G3_ + 16 * H_];   // final gates [b][col] + gi_n [b][k]
__device__ float g_alignpart[2][B_][T_];        // s@W_s partials [half][b][j]
__device__ float g_cat [T_ * B_ * CAT_];        // [s_new | y_emb | c]
__device__ float g_tt  [T_ * B_ * 2 * MO_];     // t_tilde
__device__ float g_tmax[T_ * B_ * MO_];         // maxout result
__device__ volatile int g_arrive[NBLK];         // per-block arrival flags
__device__ volatile unsigned g_barsense;        // release word

// ---------------------------------------------------------------------------
__global__ void init_kernel() {
    int i = blockIdx.x * blockDim.x + threadIdx.x;
    if (i < B_ * H_) g_s[i] = 0.0f;
    if (i < 2 * B_ * T_) ((float*)g_alignpart)[i] = 0.0f;
    if (i < NBLK) g_arrive[i] = 0;
    if (i == 0) g_barsense = 0;
}

// ---------------- tf32 helpers ----------------------------------------------
__device__ __forceinline__ unsigned f2tf(float f) {
    unsigned r; asm("cvt.rna.tf32.f32 %0, %1;" : "=r"(r) : "f"(f)); return r;
}

// ---------------- tf32 tensor-core GEMM, 128x128x16, double-buffered --------
template <bool PERMUTE>
__global__ __launch_bounds__(256, 2)
void mma_gemm_kernel(const float* __restrict__ A, int lda,
                     const float* __restrict__ Bm, int ldb,
                     float* __restrict__ C, int ldc,
                     const float* __restrict__ bias, int K, int ncols)
{
    __shared__ unsigned As[2][128][20];   // m-major, pad 20
    __shared__ unsigned Bs[2][16][136];   // k-major, pad 136

    const int tid = threadIdx.x;
    const int wid = tid >> 5, lane = tid & 31;
    const int wm = wid & 3, wn = wid >> 2;          // warps 4(M) x 2(N)
    const int m0 = blockIdx.y * 128, n0 = blockIdx.x * 128;

    const int arow = tid >> 2;                      // 0..63 (+64)
    const int acol = (tid & 3) * 4;
    const int brow = tid >> 5;                      // 0..7 (+8)
    const int bcol = lane * 4;
    int colb = n0 + bcol;
    if (colb > ncols - 4) colb = ncols - 4;         // clamp (ncols mult of 4)

    float acc[2][8][4];
#pragma unroll
    for (int mi = 0; mi < 2; mi++)
#pragma unroll
        for (int ni = 0; ni < 8; ni++)
#pragma unroll
            for (int u = 0; u < 4; u++) acc[mi][ni][u] = 0.0f;

    float4 a0v, a1v, b0v, b1v;

    auto loadT = [&](int k0) {
        a0v = *reinterpret_cast<const float4*>(&A[(size_t)(m0 + arow) * lda + k0 + acol]);
        a1v = *reinterpret_cast<const float4*>(&A[(size_t)(m0 + arow + 64) * lda + k0 + acol]);
        b0v = *reinterpret_cast<const float4*>(&Bm[(size_t)(k0 + brow) * ldb + colb]);
        b1v = *reinterpret_cast<const float4*>(&Bm[(size_t)(k0 + brow + 8) * ldb + colb]);
    };
    auto stage = [&](int p) {
        As[p][arow][acol + 0] = f2tf(a0v.x); As[p][arow][acol + 1] = f2tf(a0v.y);
        As[p][arow][acol + 2] = f2tf(a0v.z); As[p][arow][acol + 3] = f2tf(a0v.w);
        As[p][arow + 64][acol + 0] = f2tf(a1v.x); As[p][arow + 64][acol + 1] = f2tf(a1v.y);
        As[p][arow + 64][acol + 2] = f2tf(a1v.z); As[p][arow + 64][acol + 3] = f2tf(a1v.w);
        Bs[p][brow][bcol + 0] = f2tf(b0v.x); Bs[p][brow][bcol + 1] = f2tf(b0v.y);
        Bs[p][brow][bcol + 2] = f2tf(b0v.z); Bs[p][brow][bcol + 3] = f2tf(b0v.w);
        Bs[p][brow + 8][bcol + 0] = f2tf(b1v.x); Bs[p][brow + 8][bcol + 1] = f2tf(b1v.y);
        Bs[p][brow + 8][bcol + 2] = f2tf(b1v.z); Bs[p][brow + 8][bcol + 3] = f2tf(b1v.w);
    };
    auto compute = [&](int p) {
#pragma unroll
        for (int k8 = 0; k8 < 2; k8++) {
            const int kb = k8 * 8;
            unsigned af[2][4], bf[8][2];
#pragma unroll
            for (int mi = 0; mi < 2; mi++) {
                int r = wm * 32 + mi * 16 + (lane >> 2);
                af[mi][0] = As[p][r][kb + (lane & 3)];
                af[mi][1] = As[p][r + 8][kb + (lane & 3)];
                af[mi][2] = As[p][r][kb + (lane & 3) + 4];
                af[mi][3] = As[p][r + 8][kb + (lane & 3) + 4];
            }
#pragma unroll
            for (int ni = 0; ni < 8; ni++) {
                int c = wn * 64 + ni * 8 + (lane >> 2);
                bf[ni][0] = Bs[p][kb + (lane & 3)][c];
                bf[ni][1] = Bs[p][kb + (lane & 3) + 4][c];
            }
#pragma unroll
            for (int mi = 0; mi < 2; mi++)
#pragma unroll
                for (int ni = 0; ni < 8; ni++) {
                    asm volatile(
                        "mma.sync.aligned.m16n8k8.row.col.f32.tf32.tf32.f32 "
                        "{%0,%1,%2,%3}, {%4,%5,%6,%7}, {%8,%9}, {%0,%1,%2,%3};"
                        : "+f"(acc[mi][ni][0]), "+f"(acc[mi][ni][1]),
                          "+f"(acc[mi][ni][2]), "+f"(acc[mi][ni][3])
                        : "r"(af[mi][0]), "r"(af[mi][1]), "r"(af[mi][2]), "r"(af[mi][3]),
                          "r"(bf[ni][0]), "r"(bf[ni][1]));
                }
        }
    };

    loadT(0); stage(0); __syncthreads();
    int buf = 0;
    for (int k0 = 16; k0 < K; k0 += 16) {
        loadT(k0);
        compute(buf);
        stage(buf ^ 1);
        __syncthreads();
        buf ^= 1;
    }
    compute(buf);

#pragma unroll
    for (int mi = 0; mi < 2; mi++) {
        int r = m0 + wm * 32 + mi * 16 + (lane >> 2);
        int r0 = PERMUTE ? ((r & (B_ - 1)) * T_ + (r >> 4)) : r;
        int r8 = r + 8;
        int r1 = PERMUTE ? ((r8 & (B_ - 1)) * T_ + (r8 >> 4)) : r8;
#pragma unroll
        for (int ni = 0; ni < 8; ni++) {
            int c = n0 + wn * 64 + ni * 8 + (lane & 3) * 2;
            if (c < ncols) {
                float bc0 = bias[c], bc1 = bias[c + 1];
                C[(size_t)r0 * ldc + c]     = acc[mi][ni][0] + bc0;
                C[(size_t)r0 * ldc + c + 1] = acc[mi][ni][1] + bc1;
                C[(size_t)r1 * ldc + c]     = acc[mi][ni][2] + bc0;
                C[(size_t)r1 * ldc + c + 1] = acc[mi][ni][3] + bc1;
            }
        }
    }
}

// ---------------- tf32 GEMM, 256x128 tile, 256 threads (vocab) --------------
__global__ __launch_bounds__(256, 1)
void mma_gemm256_kernel(const float* __restrict__ A, int lda,
                        const float* __restrict__ Bm, int ldb,
                        float* __restrict__ C, int ldc,
                        const float* __restrict__ bias, int K, int ncols)
{
    extern __shared__ unsigned char gsm[];
    unsigned (*As)[256][20] = (unsigned(*)[256][20])gsm;              // m-major
    unsigned (*Bs)[16][136] = (unsigned(*)[16][136])(gsm + G2_AS_BYTES);

    const int tid = threadIdx.x;
    const int wid = tid >> 5, lane = tid & 31;
    const int wm = wid & 3, wn = wid >> 2;          // warps 4(M) x 2(N)
    const int m0 = blockIdx.y * 256, n0 = blockIdx.x * 128;

    const int arow = tid >> 2;                      // 0..63 (+64,+128,+192)
    const int acol = (tid & 3) * 4;
    const int brow = tid >> 5;                      // 0..7 (+8)
    const int bcol = lane * 4;
    int colb = n0 + bcol;
    if (colb > ncols - 4) colb = ncols - 4;

    float acc[4][8][4];
#pragma unroll
    for (int mi = 0; mi < 4; mi++)
#pragma unroll
        for (int ni = 0; ni < 8; ni++)
#pragma unroll
            for (int u = 0; u < 4; u++) acc[mi][ni][u] = 0.0f;

    float4 av[4];
    float4 b0v, b1v;

    auto loadT = [&](int k0) {
#pragma unroll
        for (int h = 0; h < 4; h++)
            av[h] = *reinterpret_cast<const float4*>(
                &A[(size_t)(m0 + h * 64 + arow) * lda + k0 + acol]);
        b0v = *reinterpret_cast<const float4*>(&Bm[(size_t)(k0 + brow) * ldb + colb]);
        b1v = *reinterpret_cast<const float4*>(&Bm[(size_t)(k0 + brow + 8) * ldb + colb]);
    };
    auto stage = [&](int p) {
#pragma unroll
        for (int h = 0; h < 4; h++) {
            const int r = h * 64 + arow;
            As[p][r][acol + 0] = f2tf(av[h].x); As[p][r][acol + 1] = f2tf(av[h].y);
            As[p][r][acol + 2] = f2tf(av[h].z); As[p][r][acol + 3] = f2tf(av[h].w);
        }
        Bs[p][brow][bcol + 0] = f2tf(b0v.x); Bs[p][brow][bcol + 1] = f2tf(b0v.y);
        Bs[p][brow][bcol + 2] = f2tf(b0v.z); Bs[p][brow][bcol + 3] = f2tf(b0v.w);
        Bs[p][brow + 8][bcol + 0] = f2tf(b1v.x); Bs[p][brow + 8][bcol + 1] = f2tf(b1v.y);
        Bs[p][brow + 8][bcol + 2] = f2tf(b1v.z); Bs[p][brow + 8][bcol + 3] = f2tf(b1v.w);
    };
    auto compute = [&](int p) {
#pragma unroll
        for (int k8 = 0; k8 < 2; k8++) {
            const int kb = k8 * 8;
            unsigned af[4][4], bf[8][2];
#pragma unroll
            for (int mi = 0; mi < 4; mi++) {
                int r = wm * 64 + mi * 16 + (lane >> 2);
                af[mi][0] = As[p][r][kb + (lane & 3)];
                af[mi][1] = As[p][r + 8][kb + (lane & 3)];
                af[mi][2] = As[p][r][kb + (lane & 3) + 4];
                af[mi][3] = As[p][r + 8][kb + (lane & 3) + 4];
            }
#pragma unroll
            for (int ni = 0; ni < 8; ni++) {
                int c = wn * 64 + ni * 8 + (lane >> 2);
                bf[ni][0] = Bs[p][kb + (lane & 3)][c];
                bf[ni][1] = Bs[p][kb + (lane & 3) + 4][c];
            }
#pragma unroll
            for (int mi = 0; mi < 4; mi++)
#pragma unroll
                for (int ni = 0; ni < 8; ni++) {
                    asm volatile(
                        "mma.sync.aligned.m16n8k8.row.col.f32.tf32.tf32.f32 "
                        "{%0,%1,%2,%3}, {%4,%5,%6,%7}, {%8,%9}, {%0,%1,%2,%3};"
                        : "+f"(acc[mi][ni][0]), "+f"(acc[mi][ni][1]),
                          "+f"(acc[mi][ni][2]), "+f"(acc[mi][ni][3])
                        : "r"(af[mi][0]), "r"(af[mi][1]), "r"(af[mi][2]), "r"(af[mi][3]),
                          "r"(bf[ni][0]), "r"(bf[ni][1]));
                }
        }
    };

    loadT(0); stage(0); __syncthreads();
    int buf = 0;
    for (int k0 = 16; k0 < K; k0 += 16) {
        loadT(k0);
        compute(buf);
        stage(buf ^ 1);
        __syncthreads();
        buf ^= 1;
    }
    compute(buf);

#pragma unroll
    for (int mi = 0; mi < 4; mi++) {
        int r = m0 + wm * 64 + mi * 16 + (lane >> 2);
        int r0 = (r & (B_ - 1)) * T_ + (r >> 4);        // PERMUTE (vocab only)
        int r8 = r + 8;
        int r1 = (r8 & (B_ - 1)) * T_ + (r8 >> 4);
#pragma unroll
        for (int ni = 0; ni < 8; ni++) {
            int c = n0 + wn * 64 + ni * 8 + (lane & 3) * 2;
            if (c < ncols) {
                float bc0 = bias[c], bc1 = bias[c + 1];
                C[(size_t)r0 * ldc + c]     = acc[mi][ni][0] + bc0;
                C[(size_t)r0 * ldc + c + 1] = acc[mi][ni][1] + bc1;
                C[(size_t)r1 * ldc + c]     = acc[mi][ni][2] + bc0;
                C[(size_t)r1 * ldc + c + 1] = acc[mi][ni][3] + bc1;
            }
        }
    }
}

// ---------------- persistent recurrence kernel ------------------------------
// Phase A (all 148 blocks): block owns ~21 cols of [W_hh|...]; computes
//   gh = s @ W_hh over FULL K=1024 (16 warps x 64-K chunks, mma, smem reduce;
//   A-fragments LDG'd straight from g_s), softmax + gi = e @ Hih (smem),
//   writes FINAL gate values: cols<2048 -> gh+gi; n-cols -> gh and gi apart.
// Phase B (blocks 0..31): 4 gpart loads per (b,k), GRU pointwise, s@W_s.
// Blocks >=32 skip the bar1 release: arrive with bar+2 and wait bar2 only.
__global__ __launch_bounds__(512, 1)
void recur_kernel(const float* __restrict__ Whh,
                  const float* __restrict__ Ws,
                  const float* __restrict__ bs,
                  const float* __restrict__ bhh)
{
    extern __shared__ unsigned char dsm[];
    unsigned* wt   = (unsigned*)dsm;                     // [1024][24] tf32
    float*    hs   = (float*)(dsm + HS_OFF2);            // Hih cols, pitch 1026
    float*    red  = (float*)(dsm + RED_OFF);            // [16][16][28]
    float*    gi_sh = (float*)(dsm + GI_OFF);            // [16][24]
    float    (*e_sh)[65] = (float(*)[65])(dsm + E_OFF2); // [16][65]
    float*    s2   = (float*)(dsm + RED_OFF);            // phase B alias
    float    (*redp)[64] = (float(*)[64])(dsm + RED_OFF + 2048);

    const int tid = threadIdx.x;
    const int bid = blockIdx.x;
    const int lane = tid & 31, wid = tid >> 5;

    // ---- column ownership (one map for Whh, Hih, outputs) ----
    const int c0 = (G3_ * bid) / NBLK, c1 = (G3_ * (bid + 1)) / NBLK;
    const int ncols = c1 - c0;                        // 20 or 21

    // ---- preload W_hh cols (tf32, pitch 24, zero-padded) ----
    for (int idx = tid; idx < 1024 * WPITCH; idx += 512) {
        const int r = idx / WPITCH, c = idx - r * WPITCH;
        float v = (c < ncols) ? Whh[(size_t)r * G3_ + c0 + c] : 0.0f;
        wt[idx] = f2tf(v);
    }
    // ---- preload Hih cols (fp32, transposed) ----
    for (int p = tid; p < 1024 * ncols; p += 512) {
        const int row = p / ncols, cl = p - row * ncols;
        hs[cl * HSPITCH + row] = g_Hih[(size_t)row * G3_ + c0 + cl];
    }
    __syncthreads();

    float* gpB = g_gpart + 16 * G3_;   // gi_n slot [16][1024]

    unsigned bar = 0;
    for (int i = 0; i < T_; i++) {
        // ================= phase A ======================================
        // (1) gh partials: warp wid handles K chunk [wid*64, wid*64+64)
        {
            float acc[3][4];
#pragma unroll
            for (int nb = 0; nb < 3; nb++)
#pragma unroll
                for (int u = 0; u < 4; u++) acc[nb][u] = 0.0f;
            const int kbase = wid * 64;
#pragma unroll
            for (int k8 = 0; k8 < 8; k8++) {
                const int kr = kbase + k8 * 8 + (lane & 3);
                unsigned af0 = f2tf(g_s[(lane >> 2) * H_ + kr]);
                unsigned af1 = f2tf(g_s[((lane >> 2) + 8) * H_ + kr]);
                unsigned af2 = f2tf(g_s[(lane >> 2) * H_ + kr + 4]);
                unsigned af3 = f2tf(g_s[((lane >> 2) + 8) * H_ + kr + 4]);
#pragma unroll
                for (int nb = 0; nb < 3; nb++) {
                    const int cc = nb * 8 + (lane >> 2);
                    unsigned bf0 = wt[kr * WPITCH + cc];
                    unsigned bf1 = wt[(kr + 4) * WPITCH + cc];
                    asm volatile(
                        "mma.sync.aligned.m16n8k8.row.col.f32.tf32.tf32.f32 "
                        "{%0,%1,%2,%3}, {%4,%5,%6,%7}, {%8,%9}, {%0,%1,%2,%3};"
                        : "+f"(acc[nb][0]), "+f"(acc[nb][1]),
                          "+f"(acc[nb][2]), "+f"(acc[nb][3])
                        : "r"(af0), "r"(af1), "r"(af2), "r"(af3),
                          "r"(bf0), "r"(bf1));
                }
            }
            float* rw = red + wid * (16 * 28);
#pragma unroll
            for (int nb = 0; nb < 3; nb++) {
                const int r = lane >> 2, cc2 = nb * 8 + (lane & 3) * 2;
                rw[r * 28 + cc2]           = acc[nb][0];
                rw[r * 28 + cc2 + 1]       = acc[nb][1];
                rw[(r + 8) * 28 + cc2]     = acc[nb][2];
                rw[(r + 8) * 28 + cc2 + 1] = acc[nb][3];
            }
        }
        // (2) softmax (first 256 threads; identical arithmetic to R9)
        if (tid < 256) {
            const int b2 = (tid >> 5) * 2 + (lane >> 4);
            const int j0 = (lane & 15) * 4;
            float a[4];
#pragma unroll
            for (int u = 0; u < 4; u++) {
                int jx = j0 + u;
                float v = bs[jx] + g_hemb[(b2 * T_ + i) * T_ + jx];
#pragma unroll
                for (int kc = 0; kc < 2; kc++) v += g_alignpart[kc][b2][jx];
                a[u] = tanhf(v);
            }
            float m = fmaxf(fmaxf(a[0], a[1]), fmaxf(a[2], a[3]));
#pragma unroll
            for (int o = 8; o > 0; o >>= 1)
                m = fmaxf(m, __shfl_xor_sync(0xffffffffu, m, o));
            float ex[4], ssum = 0.0f;
#pragma unroll
            for (int u = 0; u < 4; u++) { ex[u] = __expf(a[u] - m); ssum += ex[u]; }
#pragma unroll
            for (int o = 8; o > 0; o >>= 1)
                ssum += __shfl_xor_sync(0xffffffffu, ssum, o);
            float inv = 1.0f / ssum;
#pragma unroll
            for (int u = 0; u < 4; u++) {
                e_sh[b2][j0 + u] = ex[u] * inv;
                if (bid == 0) g_E[(i * B_ + b2) * T_ + j0 + u] = ex[u] * inv;
            }
        }
        __syncthreads();
        // (3) gi = e @ Hih (smem) -> gi_sh
        for (int p = tid; p < 16 * ncols; p += 512) {
            const int b = p / ncols, cl = p - b * ncols;
            const float* hrow = hs + cl * HSPITCH + b * 64;
            float a0 = 0.0f, a1 = 0.0f;
#pragma unroll
            for (int t = 0; t < 64; t += 4) {
                float2 h0 = *reinterpret_cast<const float2*>(hrow + t);
                float2 h1 = *reinterpret_cast<const float2*>(hrow + t + 2);
                a0 += e_sh[b][t] * h0.x + e_sh[b][t + 1] * h0.y;
                a1 += e_sh[b][t + 2] * h1.x + e_sh[b][t + 3] * h1.y;
            }
            gi_sh[b * 24 + cl] = a0 + a1;
        }
        __syncthreads();
        // (4) reduce 16 warp-partials, combine, write final gates
        if (tid < 16 * ncols) {
            const int b = tid & 15, c = tid >> 4;
            float gh = 0.0f;
#pragma unroll
            for (int w = 0; w < 16; w++) gh += red[w * (16 * 28) + b * 28 + c];
            const float gi = gi_sh[b * 24 + c];
            const int cg = c0 + c;
            if (cg < 2 * H_) {
                g_gpart[(size_t)b * G3_ + cg] = gh + gi;      // r,z combined
            } else {
                g_gpart[(size_t)b * G3_ + cg] = gh;           // gh_n
                gpB[b * H_ + (cg - 2 * H_)] = gi;             // gi_n
            }
        }
        // ================= barrier 1 (+ skip path) ======================
        __syncthreads();
        if (bid == 0) {
            if (tid > 0 && tid < NBLK)
                while ((unsigned)g_arrive[tid] < bar + 1) __nanosleep(64);
            __syncthreads();
            if (tid == 0) { __threadfence(); g_barsense = bar + 1; }
            __syncthreads();
        } else if (bid < 32) {
            if (tid == 0) {
                __threadfence();
                g_arrive[bid] = (int)(bar + 1);
                while (g_barsense < bar + 1) __nanosleep(64);
                __threadfence();
            }
            __syncthreads();
        } else {
            // not a phase-B worker: arrive for BOTH barriers, wait only bar2
            if (tid == 0) {
                __threadfence();
                g_arrive[bid] = (int)(bar + 2);
                while (g_barsense < bar + 2) __nanosleep(64);
                __threadfence();
            }
            __syncthreads();
        }
        // ================= phase B (blocks 0..31) =======================
        if (bid < 32) {
            const int b = bid >> 1, hf = bid & 1;
            const int k = hf * 512 + tid;

            const float grz0 = g_gpart[(size_t)b * G3_ + k];
            const float grz1 = g_gpart[(size_t)b * G3_ + H_ + k];
            const float ghn  = g_gpart[(size_t)b * G3_ + 2 * H_ + k];
            const float gin  = gpB[b * H_ + k];

            const float gr = bhh[k] + grz0;
            const float gz = bhh[H_ + k] + grz1;
            const float hn = bhh[2 * H_ + k] + ghn;
            const float r = 1.0f / (1.0f + __expf(-gr));
            const float z = 1.0f / (1.0f + __expf(-gz));
            const float n = tanhf(gin + r * hn);
            const float sold = g_s[b * H_ + k];
            const float snew = (1.0f - z) * n + z * sold;
            g_s[b * H_ + k] = snew;
            g_cat[(size_t)(i * B_ + b) * CAT_ + k] = snew;

            s2[tid] = snew;
            __syncthreads();
            const int j = tid & 63, sub = tid >> 6;     // 8 subs x 64 j
            float a = 0.0f;
#pragma unroll 8
            for (int kk = 0; kk < 64; kk++)
                a += s2[sub * 64 + kk] *
                     Ws[(size_t)(hf * 512 + sub * 64 + kk) * T_ + j];
            redp[sub][j] = a;
            __syncthreads();
            if (tid < 64)
                g_alignpart[hf][b][tid] =
                    redp[0][tid] + redp[1][tid] + redp[2][tid] + redp[3][tid] +
                    redp[4][tid] + redp[5][tid] + redp[6][tid] + redp[7][tid];
            // ---- barrier 2 ----
            __syncthreads();
            if (bid == 0) {
                if (tid > 0 && tid < NBLK)
                    while ((unsigned)g_arrive[tid] < bar + 2) __nanosleep(64);
                __syncthreads();
                if (tid == 0) { __threadfence(); g_barsense = bar + 2; }
                __syncthreads();
            } else {
                if (tid == 0) {
                    __threadfence();
                    g_arrive[bid] = (int)(bar + 2);
                    while (g_barsense < bar + 2) __nanosleep(64);
                    __threadfence();
                }
                __syncthreads();
            }
        }
        bar += 2;
    }
}

// ---------------- batched context: c[i,b,:] = e[i,b,:] @ h[b] ---------------
__global__ __launch_bounds__(128)
void ctx_kernel(const float* __restrict__ h)
{
    const int b = blockIdx.x, dc = blockIdx.y, tid = threadIdx.x;
    __shared__ float sh_h[T_][128];
    __shared__ float e_sh[T_];
    const int dbase = dc * 128;
    for (int t = 0; t < T_; t++)
        sh_h[t][tid] = h[(size_t)(b * T_ + t) * D_ + dbase + tid];
    __syncthreads();
    for (int i = 0; i < T_; i++) {
        if (tid < 64) e_sh[tid] = g_E[(i * B_ + b) * T_ + tid];
        __syncthreads();
        float acc = 0.0f;
#pragma unroll 8
        for (int t = 0; t < T_; t++) acc += e_sh[t] * sh_h[t][tid];
        g_cat[(size_t)(i * B_ + b) * CAT_ + H_ + EMB_ + dbase + tid] = acc;
        __syncthreads();
    }
}

// ---------------- maxout ----------------------------------------------------
__global__ void maxout_kernel()
{
    const int idx = blockIdx.x * blockDim.x + threadIdx.x;
    const int r = idx >> 10, m = idx & (MO_ - 1);
    g_tmax[idx] = fmaxf(g_tt[(size_t)r * 2 * MO_ + m],
                        g_tt[(size_t)r * 2 * MO_ + MO_ + m]);
}

// ---------------------------------------------------------------------------
extern "C" void kernel_launch(void* const* d_in, const int* in_sizes, int n_in,
                              void* d_out, int out_size)
{
    (void)in_sizes; (void)n_in; (void)out_size;
    const float* h     = (const float*)d_in[0];
    const float* W_h   = (const float*)d_in[1];
    const float* b_h   = (const float*)d_in[2];
    const float* W_s   = (const float*)d_in[3];
    const float* b_s   = (const float*)d_in[4];
    const float* W_ih  = (const float*)d_in[5];
    const float* b_ih  = (const float*)d_in[6];
    const float* W_hh  = (const float*)d_in[7];
    const float* b_hh  = (const float*)d_in[8];
    const float* W_emb = (const float*)d_in[9];
    const float* b_emb = (const float*)d_in[10];
    const float* W_t   = (const float*)d_in[11];
    const float* b_t   = (const float*)d_in[12];
    const float* W_out = (const float*)d_in[13];
    const float* b_out = (const float*)d_in[14];
    float* out = (float*)d_out;

    float *p_hemb, *p_Hih, *p_cat, *p_tt, *p_tmax;
    cudaGetSymbolAddress((void**)&p_hemb, g_hemb);
    cudaGetSymbolAddress((void**)&p_Hih,  g_Hih);
    cudaGetSymbolAddress((void**)&p_cat,  g_cat);
    cudaGetSymbolAddress((void**)&p_tt,   g_tt);
    cudaGetSymbolAddress((void**)&p_tmax, g_tmax);

    static int smem_set = 0;
    if (!smem_set) {
        cudaFuncSetAttribute(recur_kernel,
                             cudaFuncAttributeMaxDynamicSharedMemorySize,
                             DSMEM2);
        cudaFuncSetAttribute(mma_gemm256_kernel,
                             cudaFuncAttributeMaxDynamicSharedMemorySize,
                             G2_SMEM);
        smem_set = 1;
    }

    init_kernel<<<(B_ * H_ + 255) / 256, 256>>>();

    // Precompute: h_emb = h@W_h+b_h (N=64, guarded) ; Hih = h@W_ih+b_ih
    mma_gemm_kernel<false><<<dim3(1, (B_ * T_) / 128), 256>>>(
        h, D_, W_h, T_, p_hemb, T_, b_h, D_, T_);
    mma_gemm_kernel<false><<<dim3(G3_ / 128, (B_ * T_) / 128), 256>>>(
        h, D_, W_ih, G3_, p_Hih, G3_, b_ih, D_, G3_);

    // Entire 64-step recurrence in ONE persistent cooperative kernel
    recur_kernel<<<NBLK, 512, DSMEM2>>>(W_hh, W_s, b_s, b_hh);

    // Batched epilogue
    ctx_kernel<<<dim3(B_, D_ / 128), 128>>>(h);
    mma_gemm_kernel<false><<<dim3(EMB_ / 128, (T_ * B_) / 128), 256>>>(
        p_cat, CAT_, W_emb, EMB_, p_cat + H_, CAT_, b_emb, H_, EMB_);
    mma_gemm_kernel<false><<<dim3(2 * MO_ / 128, (T_ * B_) / 128), 256>>>(
        p_cat, CAT_, W_t, 2 * MO_, p_tt, 2 * MO_, b_t, CAT_, 2 * MO_);
    maxout_kernel<<<(T_ * B_ * MO_) / 256, 256>>>();
    // Vocab GEMM: 256x128 tiles, permuted rows
    mma_gemm256_kernel<<<dim3(V_ / 128, (T_ * B_) / 256), 256, G2_SMEM>>>(
        p_tmax, MO_, W_out, V_, out, V_, b_out, MO_, V_);
}

// round 11
// speedup vs baseline: 1.0545x; 1.0545x over previous
#include <cuda_runtime.h>
#include <cuda_bf16.h>
#include <math.h>

// Problem constants
#define B_    16
#define T_    64
#define H_    1024
#define D_    2048      // 2H
#define EMB_  512
#define MO_   1024      // maxout units
#define V_    32000
#define G3_   3072      // 3H
#define CAT_  3584      // H + EMB + D
#define NBLK  148       // persistent grid (<= SM count => co-resident)

// Dynamic smem layout for recur_kernel (bytes)  [R8 layout]
#define WT_ELEMS   (128 * 72)            // one W_hh tile, tf32, padded
#define WHH_BYTES  (3 * WT_ELEMS * 4)    // 110592
#define HSPITCH    1026                  // bank-padded Hih row (floats)
#define HS_OFF     WHH_BYTES
#define HS_BYTES   (21 * HSPITCH * 4 + 24)   // 86208
#define SA_OFF     (WHH_BYTES + HS_BYTES)    // 196800  (s tile / phase-B scratch)
#define PART_OFF   (SA_OFF + 8704)           // 205504  (2 x 16 x 66 reduce)
#define E_OFF      (PART_OFF + 8448)         // 213952  (e weights)
#define DSMEM_BYTES (E_OFF + 4160)           // 218112

// Dynamic smem for the 256x128 GEMM (bytes)  [R9 tail]
#define G2_AS_BYTES (2 * 256 * 20 * 4)       // 40960
#define G2_BS_BYTES (2 * 16 * 136 * 4)       // 17408
#define G2_SMEM     (G2_AS_BYTES + G2_BS_BYTES)  // 58368

// ---------------- scratch (device globals) ----------------------------------
__device__ float g_hemb[B_ * T_ * T_];          // h @ W_h + b_h      [b*T+t][j]
__device__ float g_Hih [B_ * T_ * G3_];         // h @ W_ih + b_ih
__device__ float g_s   [B_ * H_];               // GRU state
__device__ float g_E   [T_ * B_ * T_];          // attention weights [i][b][t]
__device__ float g_gpart[9 * B_ * G3_];         // gate partials [q][b][col]
__device__ float g_alignpart[2][B_][T_];        // s@W_s partials [half][b][j]
__device__ float g_cat [T_ * B_ * CAT_];        // [s_new | y_emb | c]
__device__ float g_tt  [T_ * B_ * 2 * MO_];     // t_tilde
__device__ float g_tmax[T_ * B_ * MO_];         // maxout result
__device__ unsigned g_barcnt;
__device__ volatile unsigned g_barsense;

// ---------------------------------------------------------------------------
__global__ void init_kernel() {
    int i = blockIdx.x * blockDim.x + threadIdx.x;
    if (i < B_ * H_) g_s[i] = 0.0f;
    if (i < 2 * B_ * T_) ((float*)g_alignpart)[i] = 0.0f;
    if (i == 0) { g_barcnt = 0; g_barsense = 0; }
}

// ---------------- tf32 helpers ----------------------------------------------
__device__ __forceinline__ unsigned f2tf(float f) {
    unsigned r; asm("cvt.rna.tf32.f32 %0, %1;" : "=r"(r) : "f"(f)); return r;
}

// ---------------- tf32 tensor-core GEMM, 128x128x16, double-buffered --------
template <bool PERMUTE>
__global__ __launch_bounds__(256, 2)
void mma_gemm_kernel(const float* __restrict__ A, int lda,
                     const float* __restrict__ Bm, int ldb,
                     float* __restrict__ C, int ldc,
                     const float* __restrict__ bias, int K, int ncols)
{
    __shared__ unsigned As[2][128][20];   // m-major, pad 20
    __shared__ unsigned Bs[2][16][136];   // k-major, pad 136

    const int tid = threadIdx.x;
    const int wid = tid >> 5, lane = tid & 31;
    const int wm = wid & 3, wn = wid >> 2;          // warps 4(M) x 2(N)
    const int m0 = blockIdx.y * 128, n0 = blockIdx.x * 128;

    const int arow = tid >> 2;                      // 0..63 (+64)
    const int acol = (tid & 3) * 4;
    const int brow = tid >> 5;                      // 0..7 (+8)
    const int bcol = lane * 4;
    int colb = n0 + bcol;
    if (colb > ncols - 4) colb = ncols - 4;         // clamp (ncols mult of 4)

    float acc[2][8][4];
#pragma unroll
    for (int mi = 0; mi < 2; mi++)
#pragma unroll
        for (int ni = 0; ni < 8; ni++)
#pragma unroll
            for (int u = 0; u < 4; u++) acc[mi][ni][u] = 0.0f;

    float4 a0v, a1v, b0v, b1v;

    auto loadT = [&](int k0) {
        a0v = *reinterpret_cast<const float4*>(&A[(size_t)(m0 + arow) * lda + k0 + acol]);
        a1v = *reinterpret_cast<const float4*>(&A[(size_t)(m0 + arow + 64) * lda + k0 + acol]);
        b0v = *reinterpret_cast<const float4*>(&Bm[(size_t)(k0 + brow) * ldb + colb]);
        b1v = *reinterpret_cast<const float4*>(&Bm[(size_t)(k0 + brow + 8) * ldb + colb]);
    };
    auto stage = [&](int p) {
        As[p][arow][acol + 0] = f2tf(a0v.x); As[p][arow][acol + 1] = f2tf(a0v.y);
        As[p][arow][acol + 2] = f2tf(a0v.z); As[p][arow][acol + 3] = f2tf(a0v.w);
        As[p][arow + 64][acol + 0] = f2tf(a1v.x); As[p][arow + 64][acol + 1] = f2tf(a1v.y);
        As[p][arow + 64][acol + 2] = f2tf(a1v.z); As[p][arow + 64][acol + 3] = f2tf(a1v.w);
        Bs[p][brow][bcol + 0] = f2tf(b0v.x); Bs[p][brow][bcol + 1] = f2tf(b0v.y);
        Bs[p][brow][bcol + 2] = f2tf(b0v.z); Bs[p][brow][bcol + 3] = f2tf(b0v.w);
        Bs[p][brow + 8][bcol + 0] = f2tf(b1v.x); Bs[p][brow + 8][bcol + 1] = f2tf(b1v.y);
        Bs[p][brow + 8][bcol + 2] = f2tf(b1v.z); Bs[p][brow + 8][bcol + 3] = f2tf(b1v.w);
    };
    auto compute = [&](int p) {
#pragma unroll
        for (int k8 = 0; k8 < 2; k8++) {
            const int kb = k8 * 8;
            unsigned af[2][4], bf[8][2];
#pragma unroll
            for (int mi = 0; mi < 2; mi++) {
                int r = wm * 32 + mi * 16 + (lane >> 2);
                af[mi][0] = As[p][r][kb + (lane & 3)];
                af[mi][1] = As[p][r + 8][kb + (lane & 3)];
                af[mi][2] = As[p][r][kb + (lane & 3) + 4];
                af[mi][3] = As[p][r + 8][kb + (lane & 3) + 4];
            }
#pragma unroll
            for (int ni = 0; ni < 8; ni++) {
                int c = wn * 64 + ni * 8 + (lane >> 2);
                bf[ni][0] = Bs[p][kb + (lane & 3)][c];
                bf[ni][1] = Bs[p][kb + (lane & 3) + 4][c];
            }
#pragma unroll
            for (int mi = 0; mi < 2; mi++)
#pragma unroll
                for (int ni = 0; ni < 8; ni++) {
                    asm volatile(
                        "mma.sync.aligned.m16n8k8.row.col.f32.tf32.tf32.f32 "
                        "{%0,%1,%2,%3}, {%4,%5,%6,%7}, {%8,%9}, {%0,%1,%2,%3};"
                        : "+f"(acc[mi][ni][0]), "+f"(acc[mi][ni][1]),
                          "+f"(acc[mi][ni][2]), "+f"(acc[mi][ni][3])
                        : "r"(af[mi][0]), "r"(af[mi][1]), "r"(af[mi][2]), "r"(af[mi][3]),
                          "r"(bf[ni][0]), "r"(bf[ni][1]));
                }
        }
    };

    loadT(0); stage(0); __syncthreads();
    int buf = 0;
    for (int k0 = 16; k0 < K; k0 += 16) {
        loadT(k0);
        compute(buf);
        stage(buf ^ 1);
        __syncthreads();
        buf ^= 1;
    }
    compute(buf);

#pragma unroll
    for (int mi = 0; mi < 2; mi++) {
        int r = m0 + wm * 32 + mi * 16 + (lane >> 2);
        int r0 = PERMUTE ? ((r & (B_ - 1)) * T_ + (r >> 4)) : r;
        int r8 = r + 8;
        int r1 = PERMUTE ? ((r8 & (B_ - 1)) * T_ + (r8 >> 4)) : r8;
#pragma unroll
        for (int ni = 0; ni < 8; ni++) {
            int c = n0 + wn * 64 + ni * 8 + (lane & 3) * 2;
            if (c < ncols) {
                float bc0 = bias[c], bc1 = bias[c + 1];
                C[(size_t)r0 * ldc + c]     = acc[mi][ni][0] + bc0;
                C[(size_t)r0 * ldc + c + 1] = acc[mi][ni][1] + bc1;
                C[(size_t)r1 * ldc + c]     = acc[mi][ni][2] + bc0;
                C[(size_t)r1 * ldc + c + 1] = acc[mi][ni][3] + bc1;
            }
        }
    }
}

// ---------------- tf32 GEMM, 256x128 tile, 256 threads (vocab) --------------
__global__ __launch_bounds__(256, 1)
void mma_gemm256_kernel(const float* __restrict__ A, int lda,
                        const float* __restrict__ Bm, int ldb,
                        float* __restrict__ C, int ldc,
                        const float* __restrict__ bias, int K, int ncols)
{
    extern __shared__ unsigned char gsm[];
    unsigned (*As)[256][20] = (unsigned(*)[256][20])gsm;              // m-major
    unsigned (*Bs)[16][136] = (unsigned(*)[16][136])(gsm + G2_AS_BYTES);

    const int tid = threadIdx.x;
    const int wid = tid >> 5, lane = tid & 31;
    const int wm = wid & 3, wn = wid >> 2;          // warps 4(M) x 2(N)
    const int m0 = blockIdx.y * 256, n0 = blockIdx.x * 128;

    const int arow = tid >> 2;                      // 0..63 (+64,+128,+192)
    const int acol = (tid & 3) * 4;
    const int brow = tid >> 5;                      // 0..7 (+8)
    const int bcol = lane * 4;
    int colb = n0 + bcol;
    if (colb > ncols - 4) colb = ncols - 4;

    float acc[4][8][4];
#pragma unroll
    for (int mi = 0; mi < 4; mi++)
#pragma unroll
        for (int ni = 0; ni < 8; ni++)
#pragma unroll
            for (int u = 0; u < 4; u++) acc[mi][ni][u] = 0.0f;

    float4 av[4];
    float4 b0v, b1v;

    auto loadT = [&](int k0) {
#pragma unroll
        for (int h = 0; h < 4; h++)
            av[h] = *reinterpret_cast<const float4*>(
                &A[(size_t)(m0 + h * 64 + arow) * lda + k0 + acol]);
        b0v = *reinterpret_cast<const float4*>(&Bm[(size_t)(k0 + brow) * ldb + colb]);
        b1v = *reinterpret_cast<const float4*>(&Bm[(size_t)(k0 + brow + 8) * ldb + colb]);
    };
    auto stage = [&](int p) {
#pragma unroll
        for (int h = 0; h < 4; h++) {
            const int r = h * 64 + arow;
            As[p][r][acol + 0] = f2tf(av[h].x); As[p][r][acol + 1] = f2tf(av[h].y);
            As[p][r][acol + 2] = f2tf(av[h].z); As[p][r][acol + 3] = f2tf(av[h].w);
        }
        Bs[p][brow][bcol + 0] = f2tf(b0v.x); Bs[p][brow][bcol + 1] = f2tf(b0v.y);
        Bs[p][brow][bcol + 2] = f2tf(b0v.z); Bs[p][brow][bcol + 3] = f2tf(b0v.w);
        Bs[p][brow + 8][bcol + 0] = f2tf(b1v.x); Bs[p][brow + 8][bcol + 1] = f2tf(b1v.y);
        Bs[p][brow + 8][bcol + 2] = f2tf(b1v.z); Bs[p][brow + 8][bcol + 3] = f2tf(b1v.w);
    };
    auto compute = [&](int p) {
#pragma unroll
        for (int k8 = 0; k8 < 2; k8++) {
            const int kb = k8 * 8;
            unsigned af[4][4], bf[8][2];
#pragma unroll
            for (int mi = 0; mi < 4; mi++) {
                int r = wm * 64 + mi * 16 + (lane >> 2);
                af[mi][0] = As[p][r][kb + (lane & 3)];
                af[mi][1] = As[p][r + 8][kb + (lane & 3)];
                af[mi][2] = As[p][r][kb + (lane & 3) + 4];
                af[mi][3] = As[p][r + 8][kb + (lane & 3) + 4];
            }
#pragma unroll
            for (int ni = 0; ni < 8; ni++) {
                int c = wn * 64 + ni * 8 + (lane >> 2);
                bf[ni][0] = Bs[p][kb + (lane & 3)][c];
                bf[ni][1] = Bs[p][kb + (lane & 3) + 4][c];
            }
#pragma unroll
            for (int mi = 0; mi < 4; mi++)
#pragma unroll
                for (int ni = 0; ni < 8; ni++) {
                    asm volatile(
                        "mma.sync.aligned.m16n8k8.row.col.f32.tf32.tf32.f32 "
                        "{%0,%1,%2,%3}, {%4,%5,%6,%7}, {%8,%9}, {%0,%1,%2,%3};"
                        : "+f"(acc[mi][ni][0]), "+f"(acc[mi][ni][1]),
                          "+f"(acc[mi][ni][2]), "+f"(acc[mi][ni][3])
                        : "r"(af[mi][0]), "r"(af[mi][1]), "r"(af[mi][2]), "r"(af[mi][3]),
                          "r"(bf[ni][0]), "r"(bf[ni][1]));
                }
        }
    };

    loadT(0); stage(0); __syncthreads();
    int buf = 0;
    for (int k0 = 16; k0 < K; k0 += 16) {
        loadT(k0);
        compute(buf);
        stage(buf ^ 1);
        __syncthreads();
        buf ^= 1;
    }
    compute(buf);

#pragma unroll
    for (int mi = 0; mi < 4; mi++) {
        int r = m0 + wm * 64 + mi * 16 + (lane >> 2);
        int r0 = (r & (B_ - 1)) * T_ + (r >> 4);        // PERMUTE (vocab only)
        int r8 = r + 8;
        int r1 = (r8 & (B_ - 1)) * T_ + (r8 >> 4);
#pragma unroll
        for (int ni = 0; ni < 8; ni++) {
            int c = n0 + wn * 64 + ni * 8 + (lane & 3) * 2;
            if (c < ncols) {
                float bc0 = bias[c], bc1 = bias[c + 1];
                C[(size_t)r0 * ldc + c]     = acc[mi][ni][0] + bc0;
                C[(size_t)r0 * ldc + c + 1] = acc[mi][ni][1] + bc1;
                C[(size_t)r1 * ldc + c]     = acc[mi][ni][2] + bc0;
                C[(size_t)r1 * ldc + c + 1] = acc[mi][ni][3] + bc1;
            }
        }
    }
}

// ---------------- grid-wide sense barrier (atomic; measured best, R8) -------
__device__ __forceinline__ void gsync(unsigned target) {
    __syncthreads();
    if (threadIdx.x == 0) {
        __threadfence();
        unsigned old = atomicAdd(&g_barcnt, 1);
        if (old == NBLK - 1) {
            g_barcnt = 0;
            __threadfence();
            g_barsense = target;
        } else {
            while (g_barsense < target) { __nanosleep(32); }
        }
        __threadfence();
    }
    __syncthreads();
}

// ---------------- persistent recurrence kernel (R8: 512 thr, q-slice) -------
__global__ __launch_bounds__(512, 1)
void recur_kernel(const float* __restrict__ Whh,
                  const float* __restrict__ Ws,
                  const float* __restrict__ bs,
                  const float* __restrict__ bhh)
{
    extern __shared__ unsigned char dsm[];
    unsigned* wt_all = (unsigned*)dsm;
    float*    hs     = (float*)(dsm + HS_OFF);
    unsigned (*sa)[136]     = (unsigned(*)[136])(dsm + SA_OFF);
    float    (*part)[16][66] = (float(*)[16][66])(dsm + PART_OFF);
    float    (*e_sh)[65]    = (float(*)[65])(dsm + E_OFF);
    float*    s2            = (float*)(dsm + SA_OFF);          // phase B alias
    float    (*redp)[64]    = (float(*)[64])(dsm + SA_OFF + 2048);

    const int tid = threadIdx.x;
    const int bid = blockIdx.x;
    const int lane = tid & 31, wid = tid >> 5;

    // ---- W_hh tile ownership: same q for all of this block's tiles ----
    const int q = bid & 7;
    const int gidx = bid >> 3;
    const int gcount = (q < 4) ? 19 : 18;
    const int c0t = gidx * 48 / gcount;
    const int c1t = (gidx + 1) * 48 / gcount;
    const int ntile = c1t - c0t;                     // 2 or 3

    // ---- Hih column ownership (independent contiguous map) ----
    const int c0h = (G3_ * bid) / NBLK, c1h = (G3_ * (bid + 1)) / NBLK;
    const int ncolsh = c1h - c0h;                    // 20 or 21

    // ---- preload W_hh tiles (tf32) ----
    for (int j = 0; j < ntile; j++) {
        const int c = c0t + j;
        const int rr = tid >> 4, c4 = (tid & 15) * 4;   // rr 0..31
        unsigned* wt = wt_all + j * WT_ELEMS;
#pragma unroll
        for (int p = 0; p < 4; p++) {
            int row = p * 32 + rr;
            float4 v = *reinterpret_cast<const float4*>(
                &Whh[(size_t)(q * 128 + row) * G3_ + c * 64 + c4]);
            wt[row * 72 + c4 + 0] = f2tf(v.x);
            wt[row * 72 + c4 + 1] = f2tf(v.y);
            wt[row * 72 + c4 + 2] = f2tf(v.z);
            wt[row * 72 + c4 + 3] = f2tf(v.w);
        }
    }
    // ---- preload Hih columns (fp32, transposed) ----
    for (int p = tid; p < 1024 * ncolsh; p += 512) {
        int row = p / ncolsh, cl = p - row * ncolsh;
        hs[cl * HSPITCH + row] = g_Hih[(size_t)row * G3_ + c0h + cl];
    }
    __syncthreads();

    const int half = wid >> 3;          // 0/1: which concurrent tile
    const int hwid = wid & 7;           // warp within the 8-warp half
    const int wk = hwid >> 2, wn = hwid & 3;

    unsigned bar = 0;
    for (int i = 0; i < T_; i++) {
        // ---- phase A: stage s (q slice) once ----
        {
            const int b = tid >> 5, c4 = (tid & 31) * 4;
            float4 v = *reinterpret_cast<const float4*>(&g_s[b * H_ + q * 128 + c4]);
            sa[b][c4 + 0] = f2tf(v.x); sa[b][c4 + 1] = f2tf(v.y);
            sa[b][c4 + 2] = f2tf(v.z); sa[b][c4 + 3] = f2tf(v.w);
        }
        __syncthreads();
        // ---- phase A: s@W_hh, two tiles at a time ----
        for (int jj = 0; jj < ntile; jj += 2) {
            const int nt = (ntile - jj < 2) ? (ntile - jj) : 2;
            const int j = jj + half;
            float acc[2][4];
#pragma unroll
            for (int ni = 0; ni < 2; ni++)
#pragma unroll
                for (int u = 0; u < 4; u++) acc[ni][u] = 0.0f;
            if (half < nt) {
                const unsigned* wt = wt_all + j * WT_ELEMS;
#pragma unroll
                for (int k8 = 0; k8 < 8; k8++) {
                    const int kb = wk * 64 + k8 * 8;
                    unsigned af[4];
                    af[0] = sa[lane >> 2][kb + (lane & 3)];
                    af[1] = sa[(lane >> 2) + 8][kb + (lane & 3)];
                    af[2] = sa[lane >> 2][kb + (lane & 3) + 4];
                    af[3] = sa[(lane >> 2) + 8][kb + (lane & 3) + 4];
#pragma unroll
                    for (int ni = 0; ni < 2; ni++) {
                        const int cc = wn * 16 + ni * 8 + (lane >> 2);
                        unsigned bf0 = wt[(kb + (lane & 3)) * 72 + cc];
                        unsigned bf1 = wt[(kb + (lane & 3) + 4) * 72 + cc];
                        asm volatile(
                            "mma.sync.aligned.m16n8k8.row.col.f32.tf32.tf32.f32 "
                            "{%0,%1,%2,%3}, {%4,%5,%6,%7}, {%8,%9}, {%0,%1,%2,%3};"
                            : "+f"(acc[ni][0]), "+f"(acc[ni][1]),
                              "+f"(acc[ni][2]), "+f"(acc[ni][3])
                            : "r"(af[0]), "r"(af[1]), "r"(af[2]), "r"(af[3]),
                              "r"(bf0), "r"(bf1));
                    }
                }
            }
            __syncthreads();
            if (half < nt && wk == 1) {
#pragma unroll
                for (int ni = 0; ni < 2; ni++) {
                    const int r = lane >> 2, cc = wn * 16 + ni * 8 + (lane & 3) * 2;
                    part[half][r][cc]         = acc[ni][0];
                    part[half][r][cc + 1]     = acc[ni][1];
                    part[half][r + 8][cc]     = acc[ni][2];
                    part[half][r + 8][cc + 1] = acc[ni][3];
                }
            }
            __syncthreads();
            if (half < nt && wk == 0) {
                const int c = c0t + j;
#pragma unroll
                for (int ni = 0; ni < 2; ni++) {
                    const int r = lane >> 2, cc = wn * 16 + ni * 8 + (lane & 3) * 2;
                    const int gc = c * 64 + cc;
                    g_gpart[(size_t)(q * 16 + r) * G3_ + gc] =
                        acc[ni][0] + part[half][r][cc];
                    g_gpart[(size_t)(q * 16 + r) * G3_ + gc + 1] =
                        acc[ni][1] + part[half][r][cc + 1];
                    g_gpart[(size_t)(q * 16 + r + 8) * G3_ + gc] =
                        acc[ni][2] + part[half][r + 8][cc];
                    g_gpart[(size_t)(q * 16 + r + 8) * G3_ + gc + 1] =
                        acc[ni][3] + part[half][r + 8][cc + 1];
                }
            }
            __syncthreads();
        }
        // ---- phase A: softmax (first 256 threads; identical arithmetic) ----
        if (tid < 256) {
            const int b2 = (tid >> 5) * 2 + (lane >> 4);
            const int j0 = (lane & 15) * 4;
            float a[4];
#pragma unroll
            for (int u = 0; u < 4; u++) {
                int jx = j0 + u;
                float v = bs[jx] + g_hemb[(b2 * T_ + i) * T_ + jx];
#pragma unroll
                for (int kc = 0; kc < 2; kc++) v += g_alignpart[kc][b2][jx];
                a[u] = tanhf(v);
            }
            float m = fmaxf(fmaxf(a[0], a[1]), fmaxf(a[2], a[3]));
#pragma unroll
            for (int o = 8; o > 0; o >>= 1)
                m = fmaxf(m, __shfl_xor_sync(0xffffffffu, m, o));
            float ex[4], ssum = 0.0f;
#pragma unroll
            for (int u = 0; u < 4; u++) { ex[u] = __expf(a[u] - m); ssum += ex[u]; }
#pragma unroll
            for (int o = 8; o > 0; o >>= 1)
                ssum += __shfl_xor_sync(0xffffffffu, ssum, o);
            float inv = 1.0f / ssum;
#pragma unroll
            for (int u = 0; u < 4; u++) {
                e_sh[b2][j0 + u] = ex[u] * inv;
                if (bid == 0) g_E[(i * B_ + b2) * T_ + j0 + u] = ex[u] * inv;
            }
        }
        __syncthreads();
        // ---- phase A: gi = e @ Hih (smem Hih) ----
        for (int p = tid; p < 16 * ncolsh; p += 512) {
            const int b = p / ncolsh, cl = p - b * ncolsh;
            const float* hrow = hs + cl * HSPITCH + b * 64;
            float a0 = 0.0f, a1 = 0.0f;
#pragma unroll
            for (int t = 0; t < 64; t += 4) {
                float2 h0 = *reinterpret_cast<const float2*>(hrow + t);
                float2 h1 = *reinterpret_cast<const float2*>(hrow + t + 2);
                a0 += e_sh[b][t] * h0.x + e_sh[b][t + 1] * h0.y;
                a1 += e_sh[b][t + 2] * h1.x + e_sh[b][t + 3] * h1.y;
            }
            g_gpart[(size_t)(8 * 16 + b) * G3_ + c0h + cl] = a0 + a1;
        }
        gsync(++bar);
        // ---- phase B: GRU pointwise + s@W_s (32 blocks x 512 k) ----
        if (bid < 32) {
            const int b = bid >> 1, hf = bid & 1;
            const int k = hf * 512 + tid;

            float gr = bhh[k], gz = bhh[H_ + k], hn = bhh[2 * H_ + k];
#pragma unroll
            for (int qq = 0; qq < 8; qq++) {
                const float* P = g_gpart + (size_t)(qq * 16 + b) * G3_;
                gr += P[k]; gz += P[H_ + k]; hn += P[2 * H_ + k];
            }
            const float* P8 = g_gpart + (size_t)(8 * 16 + b) * G3_;
            gr += P8[k]; gz += P8[H_ + k];
            float inn = P8[2 * H_ + k];

            float r = 1.0f / (1.0f + __expf(-gr));
            float z = 1.0f / (1.0f + __expf(-gz));
            float n = tanhf(inn + r * hn);
            float sold = g_s[b * H_ + k];
            float snew = (1.0f - z) * n + z * sold;
            g_s[b * H_ + k] = snew;
            g_cat[(size_t)(i * B_ + b) * CAT_ + k] = snew;

            s2[tid] = snew;
            __syncthreads();
            const int j = tid & 63, sub = tid >> 6;     // 8 subs x 64 j
            float a = 0.0f;
#pragma unroll 8
            for (int kk = 0; kk < 64; kk++)
                a += s2[sub * 64 + kk] *
                     Ws[(size_t)(hf * 512 + sub * 64 + kk) * T_ + j];
            redp[sub][j] = a;
            __syncthreads();
            if (tid < 64)
                g_alignpart[hf][b][tid] =
                    redp[0][tid] + redp[1][tid] + redp[2][tid] + redp[3][tid] +
                    redp[4][tid] + redp[5][tid] + redp[6][tid] + redp[7][tid];
        }
        gsync(++bar);
    }
}

// ---------------- batched context: c[i,b,:] = e[i,b,:] @ h[b] ---------------
__global__ __launch_bounds__(128)
void ctx_kernel(const float* __restrict__ h)
{
    const int b = blockIdx.x, dc = blockIdx.y, tid = threadIdx.x;
    __shared__ float sh_h[T_][128];
    __shared__ float e_sh[T_];
    const int dbase = dc * 128;
    for (int t = 0; t < T_; t++)
        sh_h[t][tid] = h[(size_t)(b * T_ + t) * D_ + dbase + tid];
    __syncthreads();
    for (int i = 0; i < T_; i++) {
        if (tid < 64) e_sh[tid] = g_E[(i * B_ + b) * T_ + tid];
        __syncthreads();
        float acc = 0.0f;
#pragma unroll 8
        for (int t = 0; t < T_; t++) acc += e_sh[t] * sh_h[t][tid];
        g_cat[(size_t)(i * B_ + b) * CAT_ + H_ + EMB_ + dbase + tid] = acc;
        __syncthreads();
    }
}

// ---------------- maxout (materialized: halves vocab-GEMM A traffic) --------
__global__ void maxout_kernel()
{
    const int idx = blockIdx.x * blockDim.x + threadIdx.x;
    const int r = idx >> 10, m = idx & (MO_ - 1);
    g_tmax[idx] = fmaxf(g_tt[(size_t)r * 2 * MO_ + m],
                        g_tt[(size_t)r * 2 * MO_ + MO_ + m]);
}

// ---------------------------------------------------------------------------
extern "C" void kernel_launch(void* const* d_in, const int* in_sizes, int n_in,
                              void* d_out, int out_size)
{
    (void)in_sizes; (void)n_in; (void)out_size;
    const float* h     = (const float*)d_in[0];
    const float* W_h   = (const float*)d_in[1];
    const float* b_h   = (const float*)d_in[2];
    const float* W_s   = (const float*)d_in[3];
    const float* b_s   = (const float*)d_in[4];
    const float* W_ih  = (const float*)d_in[5];
    const float* b_ih  = (const float*)d_in[6];
    const float* W_hh  = (const float*)d_in[7];
    const float* b_hh  = (const float*)d_in[8];
    const float* W_emb = (const float*)d_in[9];
    const float* b_emb = (const float*)d_in[10];
    const float* W_t   = (const float*)d_in[11];
    const float* b_t   = (const float*)d_in[12];
    const float* W_out = (const float*)d_in[13];
    const float* b_out = (const float*)d_in[14];
    float* out = (float*)d_out;

    float *p_hemb, *p_Hih, *p_cat, *p_tt, *p_tmax;
    cudaGetSymbolAddress((void**)&p_hemb, g_hemb);
    cudaGetSymbolAddress((void**)&p_Hih,  g_Hih);
    cudaGetSymbolAddress((void**)&p_cat,  g_cat);
    cudaGetSymbolAddress((void**)&p_tt,   g_tt);
    cudaGetSymbolAddress((void**)&p_tmax, g_tmax);

    static int smem_set = 0;
    if (!smem_set) {
        cudaFuncSetAttribute(recur_kernel,
                             cudaFuncAttributeMaxDynamicSharedMemorySize,
                             DSMEM_BYTES);
        cudaFuncSetAttribute(mma_gemm256_kernel,
                             cudaFuncAttributeMaxDynamicSharedMemorySize,
                             G2_SMEM);
        smem_set = 1;
    }

    init_kernel<<<(B_ * H_ + 255) / 256, 256>>>();

    // Precompute: h_emb = h@W_h+b_h (N=64, guarded) ; Hih = h@W_ih+b_ih
    mma_gemm_kernel<false><<<dim3(1, (B_ * T_) / 128), 256>>>(
        h, D_, W_h, T_, p_hemb, T_, b_h, D_, T_);
    mma_gemm_kernel<false><<<dim3(G3_ / 128, (B_ * T_) / 128), 256>>>(
        h, D_, W_ih, G3_, p_Hih, G3_, b_ih, D_, G3_);

    // Entire 64-step recurrence in ONE persistent cooperative kernel
    recur_kernel<<<NBLK, 512, DSMEM_BYTES>>>(W_hh, W_s, b_s, b_hh);

    // Batched epilogue
    ctx_kernel<<<dim3(B_, D_ / 128), 128>>>(h);
    mma_gemm_kernel<false><<<dim3(EMB_ / 128, (T_ * B_) / 128), 256>>>(
        p_cat, CAT_, W_emb, EMB_, p_cat + H_, CAT_, b_emb, H_, EMB_);
    mma_gemm_kernel<false><<<dim3(2 * MO_ / 128, (T_ * B_) / 128), 256>>>(
        p_cat, CAT_, W_t, 2 * MO_, p_tt, 2 * MO_, b_t, CAT_, 2 * MO_);
    maxout_kernel<<<(T_ * B_ * MO_) / 256, 256>>>();
    // Vocab GEMM: 256x128 tiles, permuted rows
    mma_gemm256_kernel<<<dim3(V_ / 128, (T_ * B_) / 256), 256, G2_SMEM>>>(
        p_tmax, MO_, W_out, V_, out, V_, b_out, MO_, V_);
}

// round 12
// speedup vs baseline: 1.2193x; 1.1562x over previous
#include <cuda_runtime.h>
#include <cuda_fp16.h>
#include <math.h>

// Problem constants
#define B_    16
#define T_    64
#define H_    1024
#define D_    2048      // 2H
#define EMB_  512
#define MO_   1024      // maxout units
#define V_    32000
#define G3_   3072      // 3H
#define CAT_  3584      // H + EMB + D
#define NBLK  148       // persistent grid (<= SM count => co-resident)

// Dynamic smem layout for recur_kernel (bytes)  [R8/R11 layout]
#define WT_ELEMS   (128 * 72)            // one W_hh tile, tf32, padded
#define WHH_BYTES  (3 * WT_ELEMS * 4)    // 110592
#define HSPITCH    1026                  // bank-padded Hih row (floats)
#define HS_OFF     WHH_BYTES
#define HS_BYTES   (21 * HSPITCH * 4 + 24)   // 86208
#define SA_OFF     (WHH_BYTES + HS_BYTES)    // 196800  (s tile / phase-B scratch)
#define PART_OFF   (SA_OFF + 8704)           // 205504  (2 x 16 x 66 reduce)
#define E_OFF      (PART_OFF + 8448)         // 213952  (e weights)
#define DSMEM_BYTES (E_OFF + 4160)           // 218112

// fp16 GEMM pitches (32-bit words)
#define HA_P  20                              // A tile pitch (rows x k-pairs)
#define HB_P  136                             // B tile pitch
// Dynamic smem for the 256x128 fp16 GEMM (bytes)
#define H2_AS_BYTES (2 * 256 * HA_P * 4)      // 40960
#define H2_BS_BYTES (2 * 16 * HB_P * 4)       // 17408
#define H2_SMEM     (H2_AS_BYTES + H2_BS_BYTES)   // 58368

// ---------------- scratch (device globals) ----------------------------------
__device__ float g_hemb[B_ * T_ * T_];          // h @ W_h + b_h      [b*T+t][j]
__device__ float g_Hih [B_ * T_ * G3_];         // h @ W_ih + b_ih
__device__ float g_s   [B_ * H_];               // GRU state
__device__ float g_E   [T_ * B_ * T_];          // attention weights [i][b][t]
__device__ float g_gpart[9 * B_ * G3_];         // gate partials [q][b][col]
__device__ float g_alignpart[2][B_][T_];        // s@W_s partials [half][b][j]
__device__ float g_cat [T_ * B_ * CAT_];        // [s_new | y_emb | c]
__device__ float g_tt  [T_ * B_ * 2 * MO_];     // t_tilde
__device__ float g_tmax[T_ * B_ * MO_];         // maxout result
__device__ unsigned g_barcnt;
__device__ volatile unsigned g_barsense;

// ---------------------------------------------------------------------------
__global__ void init_kernel() {
    int i = blockIdx.x * blockDim.x + threadIdx.x;
    if (i < B_ * H_) g_s[i] = 0.0f;
    if (i < 2 * B_ * T_) ((float*)g_alignpart)[i] = 0.0f;
    if (i == 0) { g_barcnt = 0; g_barsense = 0; }
}

// ---------------- helpers ----------------------------------------------------
__device__ __forceinline__ unsigned f2tf(float f) {
    unsigned r; asm("cvt.rna.tf32.f32 %0, %1;" : "=r"(r) : "f"(f)); return r;
}
__device__ __forceinline__ unsigned f2h2(float a, float b) {
    __half2 h = __floats2half2_rn(a, b);
    return *reinterpret_cast<unsigned*>(&h);
}
#define HMMA16(d, a, b)                                                     \
    asm volatile(                                                           \
        "mma.sync.aligned.m16n8k16.row.col.f32.f16.f16.f32 "                \
        "{%0,%1,%2,%3}, {%4,%5,%6,%7}, {%8,%9}, {%0,%1,%2,%3};"             \
        : "+f"(d[0]), "+f"(d[1]), "+f"(d[2]), "+f"(d[3])                    \
        : "r"(a[0]), "r"(a[1]), "r"(a[2]), "r"(a[3]), "r"(b[0]), "r"(b[1]))

// ---------------- fp16 tensor GEMM, 128x128x32, double-buffered -------------
template <bool PERMUTE>
__global__ __launch_bounds__(256, 2)
void hmma_gemm_kernel(const float* __restrict__ A, int lda,
                      const float* __restrict__ Bm, int ldb,
                      float* __restrict__ C, int ldc,
                      const float* __restrict__ bias, int K, int ncols)
{
    __shared__ unsigned As[2][128][HA_P];   // f16x2 words, k-pairs
    __shared__ unsigned Bs[2][16][HB_P];    // word(kp, n) = (B[2kp][n], B[2kp+1][n])

    const int tid = threadIdx.x;
    const int wid = tid >> 5, lane = tid & 31;
    const int wm = wid & 3, wn = wid >> 2;          // warps 4(M) x 2(N)
    const int m0 = blockIdx.y * 128, n0 = blockIdx.x * 128;

    const int arow = tid >> 1, ak = (tid & 1) * 16; // A: 128 rows x 32 k
    const int kp = tid >> 4,  bc = (tid & 15) * 8;  // B: 16 k-pairs x 128 n
    int colb = n0 + bc;
    if (colb > ncols - 8) colb = ncols - 8;         // clamp (ncols mult of 8)

    float acc[2][8][4];
#pragma unroll
    for (int mi = 0; mi < 2; mi++)
#pragma unroll
        for (int ni = 0; ni < 8; ni++)
#pragma unroll
            for (int u = 0; u < 4; u++) acc[mi][ni][u] = 0.0f;

    float4 av[4], b0v[2], b1v[2];

    auto loadT = [&](int k0) {
#pragma unroll
        for (int j = 0; j < 4; j++)
            av[j] = *reinterpret_cast<const float4*>(
                &A[(size_t)(m0 + arow) * lda + k0 + ak + j * 4]);
#pragma unroll
        for (int j = 0; j < 2; j++) {
            b0v[j] = *reinterpret_cast<const float4*>(
                &Bm[(size_t)(k0 + 2 * kp) * ldb + colb + j * 4]);
            b1v[j] = *reinterpret_cast<const float4*>(
                &Bm[(size_t)(k0 + 2 * kp + 1) * ldb + colb + j * 4]);
        }
    };
    auto stage = [&](int p) {
        uint4 w0 = make_uint4(f2h2(av[0].x, av[0].y), f2h2(av[0].z, av[0].w),
                              f2h2(av[1].x, av[1].y), f2h2(av[1].z, av[1].w));
        uint4 w1 = make_uint4(f2h2(av[2].x, av[2].y), f2h2(av[2].z, av[2].w),
                              f2h2(av[3].x, av[3].y), f2h2(av[3].z, av[3].w));
        *reinterpret_cast<uint4*>(&As[p][arow][ak / 2])     = w0;
        *reinterpret_cast<uint4*>(&As[p][arow][ak / 2 + 4]) = w1;
        uint4 u0 = make_uint4(f2h2(b0v[0].x, b1v[0].x), f2h2(b0v[0].y, b1v[0].y),
                              f2h2(b0v[0].z, b1v[0].z), f2h2(b0v[0].w, b1v[0].w));
        uint4 u1 = make_uint4(f2h2(b0v[1].x, b1v[1].x), f2h2(b0v[1].y, b1v[1].y),
                              f2h2(b0v[1].z, b1v[1].z), f2h2(b0v[1].w, b1v[1].w));
        *reinterpret_cast<uint4*>(&Bs[p][kp][bc])     = u0;
        *reinterpret_cast<uint4*>(&Bs[p][kp][bc + 4]) = u1;
    };
    auto compute = [&](int p) {
#pragma unroll
        for (int ks = 0; ks < 2; ks++) {
            unsigned af[2][4], bf[8][2];
#pragma unroll
            for (int mi = 0; mi < 2; mi++) {
                int r = wm * 32 + mi * 16 + (lane >> 2);
                af[mi][0] = As[p][r][ks * 8 + (lane & 3)];
                af[mi][1] = As[p][r + 8][ks * 8 + (lane & 3)];
                af[mi][2] = As[p][r][ks * 8 + (lane & 3) + 4];
                af[mi][3] = As[p][r + 8][ks * 8 + (lane & 3) + 4];
            }
#pragma unroll
            for (int ni = 0; ni < 8; ni++) {
                int c = wn * 64 + ni * 8 + (lane >> 2);
                bf[ni][0] = Bs[p][ks * 8 + (lane & 3)][c];
                bf[ni][1] = Bs[p][ks * 8 + (lane & 3) + 4][c];
            }
#pragma unroll
            for (int mi = 0; mi < 2; mi++)
#pragma unroll
                for (int ni = 0; ni < 8; ni++)
                    HMMA16(acc[mi][ni], af[mi], bf[ni]);
        }
    };

    loadT(0); stage(0); __syncthreads();
    int buf = 0;
    for (int k0 = 32; k0 < K; k0 += 32) {
        loadT(k0);
        compute(buf);
        stage(buf ^ 1);
        __syncthreads();
        buf ^= 1;
    }
    compute(buf);

#pragma unroll
    for (int mi = 0; mi < 2; mi++) {
        int r = m0 + wm * 32 + mi * 16 + (lane >> 2);
        int r0 = PERMUTE ? ((r & (B_ - 1)) * T_ + (r >> 4)) : r;
        int r8 = r + 8;
        int r1 = PERMUTE ? ((r8 & (B_ - 1)) * T_ + (r8 >> 4)) : r8;
#pragma unroll
        for (int ni = 0; ni < 8; ni++) {
            int c = n0 + wn * 64 + ni * 8 + (lane & 3) * 2;
            if (c < ncols) {
                float bc0 = bias[c], bc1 = bias[c + 1];
                C[(size_t)r0 * ldc + c]     = acc[mi][ni][0] + bc0;
                C[(size_t)r0 * ldc + c + 1] = acc[mi][ni][1] + bc1;
                C[(size_t)r1 * ldc + c]     = acc[mi][ni][2] + bc0;
                C[(size_t)r1 * ldc + c + 1] = acc[mi][ni][3] + bc1;
            }
        }
    }
}

// ---------------- fp16 GEMM, 256x128x32 tile (vocab, permuted rows) ---------
__global__ __launch_bounds__(256, 1)
void hmma_gemm256_kernel(const float* __restrict__ A, int lda,
                         const float* __restrict__ Bm, int ldb,
                         float* __restrict__ C, int ldc,
                         const float* __restrict__ bias, int K, int ncols)
{
    extern __shared__ unsigned char gsm[];
    unsigned (*As)[256][HA_P] = (unsigned(*)[256][HA_P])gsm;
    unsigned (*Bs)[16][HB_P]  = (unsigned(*)[16][HB_P])(gsm + H2_AS_BYTES);

    const int tid = threadIdx.x;
    const int wid = tid >> 5, lane = tid & 31;
    const int wm = wid & 3, wn = wid >> 2;          // warps 4(M) x 2(N)
    const int m0 = blockIdx.y * 256, n0 = blockIdx.x * 128;

    const int arow = tid >> 1, ak = (tid & 1) * 16; // rows arow, arow+128
    const int kp = tid >> 4,  bc = (tid & 15) * 8;
    int colb = n0 + bc;
    if (colb > ncols - 8) colb = ncols - 8;

    float acc[4][8][4];
#pragma unroll
    for (int mi = 0; mi < 4; mi++)
#pragma unroll
        for (int ni = 0; ni < 8; ni++)
#pragma unroll
            for (int u = 0; u < 4; u++) acc[mi][ni][u] = 0.0f;

    float4 av[8], b0v[2], b1v[2];

    auto loadT = [&](int k0) {
#pragma unroll
        for (int j = 0; j < 4; j++) {
            av[j]     = *reinterpret_cast<const float4*>(
                &A[(size_t)(m0 + arow) * lda + k0 + ak + j * 4]);
            av[j + 4] = *reinterpret_cast<const float4*>(
                &A[(size_t)(m0 + arow + 128) * lda + k0 + ak + j * 4]);
        }
#pragma unroll
        for (int j = 0; j < 2; j++) {
            b0v[j] = *reinterpret_cast<const float4*>(
                &Bm[(size_t)(k0 + 2 * kp) * ldb + colb + j * 4]);
            b1v[j] = *reinterpret_cast<const float4*>(
                &Bm[(size_t)(k0 + 2 * kp + 1) * ldb + colb + j * 4]);
        }
    };
    auto stage = [&](int p) {
#pragma unroll
        for (int h = 0; h < 2; h++) {
            const int r = arow + h * 128;
            uint4 w0 = make_uint4(
                f2h2(av[h*4+0].x, av[h*4+0].y), f2h2(av[h*4+0].z, av[h*4+0].w),
                f2h2(av[h*4+1].x, av[h*4+1].y), f2h2(av[h*4+1].z, av[h*4+1].w));
            uint4 w1 = make_uint4(
                f2h2(av[h*4+2].x, av[h*4+2].y), f2h2(av[h*4+2].z, av[h*4+2].w),
                f2h2(av[h*4+3].x, av[h*4+3].y), f2h2(av[h*4+3].z, av[h*4+3].w));
            *reinterpret_cast<uint4*>(&As[p][r][ak / 2])     = w0;
            *reinterpret_cast<uint4*>(&As[p][r][ak / 2 + 4]) = w1;
        }
        uint4 u0 = make_uint4(f2h2(b0v[0].x, b1v[0].x), f2h2(b0v[0].y, b1v[0].y),
                              f2h2(b0v[0].z, b1v[0].z), f2h2(b0v[0].w, b1v[0].w));
        uint4 u1 = make_uint4(f2h2(b0v[1].x, b1v[1].x), f2h2(b0v[1].y, b1v[1].y),
                              f2h2(b0v[1].z, b1v[1].z), f2h2(b0v[1].w, b1v[1].w));
        *reinterpret_cast<uint4*>(&Bs[p][kp][bc])     = u0;
        *reinterpret_cast<uint4*>(&Bs[p][kp][bc + 4]) = u1;
    };
    auto compute = [&](int p) {
#pragma unroll
        for (int ks = 0; ks < 2; ks++) {
            unsigned af[4][4], bf[8][2];
#pragma unroll
            for (int mi = 0; mi < 4; mi++) {
                int r = wm * 64 + mi * 16 + (lane >> 2);
                af[mi][0] = As[p][r][ks * 8 + (lane & 3)];
                af[mi][1] = As[p][r + 8][ks * 8 + (lane & 3)];
                af[mi][2] = As[p][r][ks * 8 + (lane & 3) + 4];
                af[mi][3] = As[p][r + 8][ks * 8 + (lane & 3) + 4];
            }
#pragma unroll
            for (int ni = 0; ni < 8; ni++) {
                int c = wn * 64 + ni * 8 + (lane >> 2);
                bf[ni][0] = Bs[p][ks * 8 + (lane & 3)][c];
                bf[ni][1] = Bs[p][ks * 8 + (lane & 3) + 4][c];
            }
#pragma unroll
            for (int mi = 0; mi < 4; mi++)
#pragma unroll
                for (int ni = 0; ni < 8; ni++)
                    HMMA16(acc[mi][ni], af[mi], bf[ni]);
        }
    };

    loadT(0); stage(0); __syncthreads();
    int buf = 0;
    for (int k0 = 32; k0 < K; k0 += 32) {
        loadT(k0);
        compute(buf);
        stage(buf ^ 1);
        __syncthreads();
        buf ^= 1;
    }
    compute(buf);

#pragma unroll
    for (int mi = 0; mi < 4; mi++) {
        int r = m0 + wm * 64 + mi * 16 + (lane >> 2);
        int r0 = (r & (B_ - 1)) * T_ + (r >> 4);        // PERMUTE
        int r8 = r + 8;
        int r1 = (r8 & (B_ - 1)) * T_ + (r8 >> 4);
#pragma unroll
        for (int ni = 0; ni < 8; ni++) {
            int c = n0 + wn * 64 + ni * 8 + (lane & 3) * 2;
            if (c < ncols) {
                float bc0 = bias[c], bc1 = bias[c + 1];
                C[(size_t)r0 * ldc + c]     = acc[mi][ni][0] + bc0;
                C[(size_t)r0 * ldc + c + 1] = acc[mi][ni][1] + bc1;
                C[(size_t)r1 * ldc + c]     = acc[mi][ni][2] + bc0;
                C[(size_t)r1 * ldc + c + 1] = acc[mi][ni][3] + bc1;
            }
        }
    }
}

// ---------------- grid-wide sense barrier (atomic; measured best) -----------
__device__ __forceinline__ void gsync(unsigned target) {
    __syncthreads();
    if (threadIdx.x == 0) {
        __threadfence();
        unsigned old = atomicAdd(&g_barcnt, 1);
        if (old == NBLK - 1) {
            g_barcnt = 0;
            __threadfence();
            g_barsense = target;
        } else {
            while (g_barsense < target) { __nanosleep(32); }
        }
        __threadfence();
    }
    __syncthreads();
}

// ---------------- persistent recurrence kernel (R11 verbatim) ---------------
__global__ __launch_bounds__(512, 1)
void recur_kernel(const float* __restrict__ Whh,
                  const float* __restrict__ Ws,
                  const float* __restrict__ bs,
                  const float* __restrict__ bhh)
{
    extern __shared__ unsigned char dsm[];
    unsigned* wt_all = (unsigned*)dsm;
    float*    hs     = (float*)(dsm + HS_OFF);
    unsigned (*sa)[136]     = (unsigned(*)[136])(dsm + SA_OFF);
    float    (*part)[16][66] = (float(*)[16][66])(dsm + PART_OFF);
    float    (*e_sh)[65]    = (float(*)[65])(dsm + E_OFF);
    float*    s2            = (float*)(dsm + SA_OFF);          // phase B alias
    float    (*redp)[64]    = (float(*)[64])(dsm + SA_OFF + 2048);

    const int tid = threadIdx.x;
    const int bid = blockIdx.x;
    const int lane = tid & 31, wid = tid >> 5;

    const int q = bid & 7;
    const int gidx = bid >> 3;
    const int gcount = (q < 4) ? 19 : 18;
    const int c0t = gidx * 48 / gcount;
    const int c1t = (gidx + 1) * 48 / gcount;
    const int ntile = c1t - c0t;                     // 2 or 3

    const int c0h = (G3_ * bid) / NBLK, c1h = (G3_ * (bid + 1)) / NBLK;
    const int ncolsh = c1h - c0h;                    // 20 or 21

    for (int j = 0; j < ntile; j++) {
        const int c = c0t + j;
        const int rr = tid >> 4, c4 = (tid & 15) * 4;
        unsigned* wt = wt_all + j * WT_ELEMS;
#pragma unroll
        for (int p = 0; p < 4; p++) {
            int row = p * 32 + rr;
            float4 v = *reinterpret_cast<const float4*>(
                &Whh[(size_t)(q * 128 + row) * G3_ + c * 64 + c4]);
            wt[row * 72 + c4 + 0] = f2tf(v.x);
            wt[row * 72 + c4 + 1] = f2tf(v.y);
            wt[row * 72 + c4 + 2] = f2tf(v.z);
            wt[row * 72 + c4 + 3] = f2tf(v.w);
        }
    }
    for (int p = tid; p < 1024 * ncolsh; p += 512) {
        int row = p / ncolsh, cl = p - row * ncolsh;
        hs[cl * HSPITCH + row] = g_Hih[(size_t)row * G3_ + c0h + cl];
    }
    __syncthreads();

    const int half = wid >> 3;
    const int hwid = wid & 7;
    const int wk = hwid >> 2, wn = hwid & 3;

    unsigned bar = 0;
    for (int i = 0; i < T_; i++) {
        {
            const int b = tid >> 5, c4 = (tid & 31) * 4;
            float4 v = *reinterpret_cast<const float4*>(&g_s[b * H_ + q * 128 + c4]);
            sa[b][c4 + 0] = f2tf(v.x); sa[b][c4 + 1] = f2tf(v.y);
            sa[b][c4 + 2] = f2tf(v.z); sa[b][c4 + 3] = f2tf(v.w);
        }
        __syncthreads();
        for (int jj = 0; jj < ntile; jj += 2) {
            const int nt = (ntile - jj < 2) ? (ntile - jj) : 2;
            const int j = jj + half;
            float acc[2][4];
#pragma unroll
            for (int ni = 0; ni < 2; ni++)
#pragma unroll
                for (int u = 0; u < 4; u++) acc[ni][u] = 0.0f;
            if (half < nt) {
                const unsigned* wt = wt_all + j * WT_ELEMS;
#pragma unroll
                for (int k8 = 0; k8 < 8; k8++) {
                    const int kb = wk * 64 + k8 * 8;
                    unsigned af[4];
                    af[0] = sa[lane >> 2][kb + (lane & 3)];
                    af[1] = sa[(lane >> 2) + 8][kb + (lane & 3)];
                    af[2] = sa[lane >> 2][kb + (lane & 3) + 4];
                    af[3] = sa[(lane >> 2) + 8][kb + (lane & 3) + 4];
#pragma unroll
                    for (int ni = 0; ni < 2; ni++) {
                        const int cc = wn * 16 + ni * 8 + (lane >> 2);
                        unsigned bf0 = wt[(kb + (lane & 3)) * 72 + cc];
                        unsigned bf1 = wt[(kb + (lane & 3) + 4) * 72 + cc];
                        asm volatile(
                            "mma.sync.aligned.m16n8k8.row.col.f32.tf32.tf32.f32 "
                            "{%0,%1,%2,%3}, {%4,%5,%6,%7}, {%8,%9}, {%0,%1,%2,%3};"
                            : "+f"(acc[ni][0]), "+f"(acc[ni][1]),
                              "+f"(acc[ni][2]), "+f"(acc[ni][3])
                            : "r"(af[0]), "r"(af[1]), "r"(af[2]), "r"(af[3]),
                              "r"(bf0), "r"(bf1));
                    }
                }
            }
            __syncthreads();
            if (half < nt && wk == 1) {
#pragma unroll
                for (int ni = 0; ni < 2; ni++) {
                    const int r = lane >> 2, cc = wn * 16 + ni * 8 + (lane & 3) * 2;
                    part[half][r][cc]         = acc[ni][0];
                    part[half][r][cc + 1]     = acc[ni][1];
                    part[half][r + 8][cc]     = acc[ni][2];
                    part[half][r + 8][cc + 1] = acc[ni][3];
                }
            }
            __syncthreads();
            if (half < nt && wk == 0) {
                const int c = c0t + j;
#pragma unroll
                for (int ni = 0; ni < 2; ni++) {
                    const int r = lane >> 2, cc = wn * 16 + ni * 8 + (lane & 3) * 2;
                    const int gc = c * 64 + cc;
                    g_gpart[(size_t)(q * 16 + r) * G3_ + gc] =
                        acc[ni][0] + part[half][r][cc];
                    g_gpart[(size_t)(q * 16 + r) * G3_ + gc + 1] =
                        acc[ni][1] + part[half][r][cc + 1];
                    g_gpart[(size_t)(q * 16 + r + 8) * G3_ + gc] =
                        acc[ni][2] + part[half][r + 8][cc];
                    g_gpart[(size_t)(q * 16 + r + 8) * G3_ + gc + 1] =
                        acc[ni][3] + part[half][r + 8][cc + 1];
                }
            }
            __syncthreads();
        }
        if (tid < 256) {
            const int b2 = (tid >> 5) * 2 + (lane >> 4);
            const int j0 = (lane & 15) * 4;
            float a[4];
#pragma unroll
            for (int u = 0; u < 4; u++) {
                int jx = j0 + u;
                float v = bs[jx] + g_hemb[(b2 * T_ + i) * T_ + jx];
#pragma unroll
                for (int kc = 0; kc < 2; kc++) v += g_alignpart[kc][b2][jx];
                a[u] = tanhf(v);
            }
            float m = fmaxf(fmaxf(a[0], a[1]), fmaxf(a[2], a[3]));
#pragma unroll
            for (int o = 8; o > 0; o >>= 1)
                m = fmaxf(m, __shfl_xor_sync(0xffffffffu, m, o));
            float ex[4], ssum = 0.0f;
#pragma unroll
            for (int u = 0; u < 4; u++) { ex[u] = __expf(a[u] - m); ssum += ex[u]; }
#pragma unroll
            for (int o = 8; o > 0; o >>= 1)
                ssum += __shfl_xor_sync(0xffffffffu, ssum, o);
            float inv = 1.0f / ssum;
#pragma unroll
            for (int u = 0; u < 4; u++) {
                e_sh[b2][j0 + u] = ex[u] * inv;
                if (bid == 0) g_E[(i * B_ + b2) * T_ + j0 + u] = ex[u] * inv;
            }
        }
        __syncthreads();
        for (int p = tid; p < 16 * ncolsh; p += 512) {
            const int b = p / ncolsh, cl = p - b * ncolsh;
            const float* hrow = hs + cl * HSPITCH + b * 64;
            float a0 = 0.0f, a1 = 0.0f;
#pragma unroll
            for (int t = 0; t < 64; t += 4) {
                float2 h0 = *reinterpret_cast<const float2*>(hrow + t);
                float2 h1 = *reinterpret_cast<const float2*>(hrow + t + 2);
                a0 += e_sh[b][t] * h0.x + e_sh[b][t + 1] * h0.y;
                a1 += e_sh[b][t + 2] * h1.x + e_sh[b][t + 3] * h1.y;
            }
            g_gpart[(size_t)(8 * 16 + b) * G3_ + c0h + cl] = a0 + a1;
        }
        gsync(++bar);
        if (bid < 32) {
            const int b = bid >> 1, hf = bid & 1;
            const int k = hf * 512 + tid;

            float gr = bhh[k], gz = bhh[H_ + k], hn = bhh[2 * H_ + k];
#pragma unroll
            for (int qq = 0; qq < 8; qq++) {
                const float* P = g_gpart + (size_t)(qq * 16 + b) * G3_;
                gr += P[k]; gz += P[H_ + k]; hn += P[2 * H_ + k];
            }
            const float* P8 = g_gpart + (size_t)(8 * 16 + b) * G3_;
            gr += P8[k]; gz += P8[H_ + k];
            float inn = P8[2 * H_ + k];

            float r = 1.0f / (1.0f + __expf(-gr));
            float z = 1.0f / (1.0f + __expf(-gz));
            float n = tanhf(inn + r * hn);
            float sold = g_s[b * H_ + k];
            float snew = (1.0f - z) * n + z * sold;
            g_s[b * H_ + k] = snew;
            g_cat[(size_t)(i * B_ + b) * CAT_ + k] = snew;

            s2[tid] = snew;
            __syncthreads();
            const int j = tid & 63, sub = tid >> 6;
            float a = 0.0f;
#pragma unroll 8
            for (int kk = 0; kk < 64; kk++)
                a += s2[sub * 64 + kk] *
                     Ws[(size_t)(hf * 512 + sub * 64 + kk) * T_ + j];
            redp[sub][j] = a;
            __syncthreads();
            if (tid < 64)
                g_alignpart[hf][b][tid] =
                    redp[0][tid] + redp[1][tid] + redp[2][tid] + redp[3][tid] +
                    redp[4][tid] + redp[5][tid] + redp[6][tid] + redp[7][tid];
        }
        gsync(++bar);
    }
}

// ---------------- batched context: c[i,b,:] = e[i,b,:] @ h[b] ---------------
__global__ __launch_bounds__(128)
void ctx_kernel(const float* __restrict__ h)
{
    const int b = blockIdx.x, dc = blockIdx.y, tid = threadIdx.x;
    __shared__ float sh_h[T_][128];
    __shared__ float e_sh[T_];
    const int dbase = dc * 128;
    for (int t = 0; t < T_; t++)
        sh_h[t][tid] = h[(size_t)(b * T_ + t) * D_ + dbase + tid];
    __syncthreads();
    for (int i = 0; i < T_; i++) {
        if (tid < 64) e_sh[tid] = g_E[(i * B_ + b) * T_ + tid];
        __syncthreads();
        float acc = 0.0f;
#pragma unroll 8
        for (int t = 0; t < T_; t++) acc += e_sh[t] * sh_h[t][tid];
        g_cat[(size_t)(i * B_ + b) * CAT_ + H_ + EMB_ + dbase + tid] = acc;
        __syncthreads();
    }
}

// ---------------- maxout ----------------------------------------------------
__global__ void maxout_kernel()
{
    const int idx = blockIdx.x * blockDim.x + threadIdx.x;
    const int r = idx >> 10, m = idx & (MO_ - 1);
    g_tmax[idx] = fmaxf(g_tt[(size_t)r * 2 * MO_ + m],
                        g_tt[(size_t)r * 2 * MO_ + MO_ + m]);
}

// ---------------------------------------------------------------------------
extern "C" void kernel_launch(void* const* d_in, const int* in_sizes, int n_in,
                              void* d_out, int out_size)
{
    (void)in_sizes; (void)n_in; (void)out_size;
    const float* h     = (const float*)d_in[0];
    const float* W_h   = (const float*)d_in[1];
    const float* b_h   = (const float*)d_in[2];
    const float* W_s   = (const float*)d_in[3];
    const float* b_s   = (const float*)d_in[4];
    const float* W_ih  = (const float*)d_in[5];
    const float* b_ih  = (const float*)d_in[6];
    const float* W_hh  = (const float*)d_in[7];
    const float* b_hh  = (const float*)d_in[8];
    const float* W_emb = (const float*)d_in[9];
    const float* b_emb = (const float*)d_in[10];
    const float* W_t   = (const float*)d_in[11];
    const float* b_t   = (const float*)d_in[12];
    const float* W_out = (const float*)d_in[13];
    const float* b_out = (const float*)d_in[14];
    float* out = (float*)d_out;

    float *p_hemb, *p_Hih, *p_cat, *p_tt, *p_tmax;
    cudaGetSymbolAddress((void**)&p_hemb, g_hemb);
    cudaGetSymbolAddress((void**)&p_Hih,  g_Hih);
    cudaGetSymbolAddress((void**)&p_cat,  g_cat);
    cudaGetSymbolAddress((void**)&p_tt,   g_tt);
    cudaGetSymbolAddress((void**)&p_tmax, g_tmax);

    static int smem_set = 0;
    if (!smem_set) {
        cudaFuncSetAttribute(recur_kernel,
                             cudaFuncAttributeMaxDynamicSharedMemorySize,
                             DSMEM_BYTES);
        cudaFuncSetAttribute(hmma_gemm256_kernel,
                             cudaFuncAttributeMaxDynamicSharedMemorySize,
                             H2_SMEM);
        smem_set = 1;
    }

    init_kernel<<<(B_ * H_ + 255) / 256, 256>>>();

    // Precompute: h_emb = h@W_h+b_h (N=64, guarded) ; Hih = h@W_ih+b_ih
    hmma_gemm_kernel<false><<<dim3(1, (B_ * T_) / 128), 256>>>(
        h, D_, W_h, T_, p_hemb, T_, b_h, D_, T_);
    hmma_gemm_kernel<false><<<dim3(G3_ / 128, (B_ * T_) / 128), 256>>>(
        h, D_, W_ih, G3_, p_Hih, G3_, b_ih, D_, G3_);

    // Entire 64-step recurrence in ONE persistent cooperative kernel
    recur_kernel<<<NBLK, 512, DSMEM_BYTES>>>(W_hh, W_s, b_s, b_hh);

    // Batched epilogue (all fp16 tensor path)
    ctx_kernel<<<dim3(B_, D_ / 128), 128>>>(h);
    hmma_gemm_kernel<false><<<dim3(EMB_ / 128, (T_ * B_) / 128), 256>>>(
        p_cat, CAT_, W_emb, EMB_, p_cat + H_, CAT_, b_emb, H_, EMB_);
    hmma_gemm_kernel<false><<<dim3(2 * MO_ / 128, (T_ * B_) / 128), 256>>>(
        p_cat, CAT_, W_t, 2 * MO_, p_tt, 2 * MO_, b_t, CAT_, 2 * MO_);
    maxout_kernel<<<(T_ * B_ * MO_) / 256, 256>>>();
    hmma_gemm256_kernel<<<dim3(V_ / 128, (T_ * B_) / 256), 256, H2_SMEM>>>(
        p_tmax, MO_, W_out, V_, out, V_, b_out, MO_, V_);
}

// round 13
// speedup vs baseline: 1.4080x; 1.1547x over previous
#include <cuda_runtime.h>
#include <cuda_fp16.h>
#include <math.h>

// Problem constants
#define B_    16
#define T_    64
#define H_    1024
#define D_    2048      // 2H
#define EMB_  512
#define MO_   1024      // maxout units
#define V_    32000
#define G3_   3072      // 3H
#define CAT_  3584      // H + EMB + D
#define NBLK  148       // persistent grid

// Dynamic smem layout for recur_kernel (bytes)  [R11 layout]
#define WT_ELEMS   (128 * 72)
#define WHH_BYTES  (3 * WT_ELEMS * 4)    // 110592
#define HSPITCH    1026
#define HS_OFF     WHH_BYTES
#define HS_BYTES   (21 * HSPITCH * 4 + 24)
#define SA_OFF     (WHH_BYTES + HS_BYTES)
#define PART_OFF   (SA_OFF + 8704)
#define E_OFF      (PART_OFF + 8448)
#define DSMEM_BYTES (E_OFF + 4160)       // 218112

// fp16 GEMM smem (3-stage pipeline, words)
#define HA_P   20
#define HB_P   136
#define H128_AS (3 * 128 * HA_P)
#define H128_SMEM ((H128_AS + 3 * 16 * HB_P) * 4)    // 56832
#define H256_AS (3 * 256 * HA_P)
#define H256_SMEM ((H256_AS + 3 * 16 * HB_P) * 4)    // 87552

// ---------------- scratch (device globals) ----------------------------------
__device__ float g_hemb[B_ * T_ * T_];
__device__ float g_Hih [B_ * T_ * G3_];
__device__ float g_s   [B_ * H_];
__device__ float g_E   [T_ * B_ * T_];
__device__ float g_gpart[9 * B_ * G3_];
__device__ float g_alignpart[2][B_][T_];
__device__ float g_cat [T_ * B_ * CAT_];
__device__ float g_tt  [T_ * B_ * 2 * MO_];
__device__ unsigned g_barcnt;
__device__ volatile unsigned g_barsense;
// packed half2 operands
__device__ unsigned g_h_p  [B_ * T_ * (D_ / 2)];      // h rows packed
__device__ unsigned g_Wh_p [(D_ / 2) * T_];
__device__ unsigned g_Wih_p[(D_ / 2) * G3_];
__device__ unsigned g_Wemb_p[(H_ / 2) * EMB_];
__device__ unsigned g_Wt_p [(CAT_ / 2) * 2 * MO_];
__device__ unsigned g_Wout_p[(MO_ / 2) * V_];
__device__ unsigned g_cath [T_ * B_ * (CAT_ / 2)];
__device__ unsigned g_tmaxh[T_ * B_ * (MO_ / 2)];

// ---------------------------------------------------------------------------
__global__ void init_kernel() {
    int i = blockIdx.x * blockDim.x + threadIdx.x;
    if (i < B_ * H_) g_s[i] = 0.0f;
    if (i < 2 * B_ * T_) ((float*)g_alignpart)[i] = 0.0f;
    if (i == 0) { g_barcnt = 0; g_barsense = 0; }
}

// ---------------- helpers ----------------------------------------------------
__device__ __forceinline__ unsigned f2tf(float f) {
    unsigned r; asm("cvt.rna.tf32.f32 %0, %1;" : "=r"(r) : "f"(f)); return r;
}
__device__ __forceinline__ unsigned f2h2(float a, float b) {
    __half2 h = __floats2half2_rn(a, b);
    return *reinterpret_cast<unsigned*>(&h);
}
__device__ __forceinline__ void cpa16(unsigned smem, const void* g) {
    asm volatile("cp.async.cg.shared.global [%0], [%1], 16;" :: "r"(smem), "l"(g));
}
#define CP_COMMIT() asm volatile("cp.async.commit_group;" ::: "memory")
#define CP_WAIT(n)  asm volatile("cp.async.wait_group %0;" :: "n"(n) : "memory")
#define HMMA16(d, a, b)                                                     \
    asm volatile(                                                           \
        "mma.sync.aligned.m16n8k16.row.col.f32.f16.f16.f32 "                \
        "{%0,%1,%2,%3}, {%4,%5,%6,%7}, {%8,%9}, {%0,%1,%2,%3};"             \
        : "+f"(d[0]), "+f"(d[1]), "+f"(d[2]), "+f"(d[3])                    \
        : "r"(a[0]), "r"(a[1]), "r"(a[2]), "r"(a[3]), "r"(b[0]), "r"(b[1]))

// ---------------- pack kernels ----------------------------------------------
// A-pack: row-major, pairs along k (flat or strided)
__global__ void pack_rows_kernel(const float* __restrict__ src,
                                 unsigned* __restrict__ dst,
                                 int rows, int nw, int src_ld, int dst_ld)
{
    int i = blockIdx.x * blockDim.x + threadIdx.x;
    if (i < rows * nw) {
        int r = i / nw, w = i - r * nw;
        float2 v = *reinterpret_cast<const float2*>(&src[(size_t)r * src_ld + 2 * w]);
        dst[(size_t)r * dst_ld + w] = f2h2(v.x, v.y);
    }
}
// B-pack: word(k2, n) = (B[2k2][n], B[2k2+1][n])
__global__ void pack_b_kernel(const float* __restrict__ src,
                              unsigned* __restrict__ dst, int K2, int N)
{
    int i = blockIdx.x * blockDim.x + threadIdx.x;
    if (i < K2 * N) {
        int k2 = i / N, n = i - k2 * N;
        dst[i] = f2h2(src[(size_t)(2 * k2) * N + n],
                      src[(size_t)(2 * k2 + 1) * N + n]);
    }
}

// ---------------- fp16 GEMM, 128x128x32, 3-stage cp.async -------------------
template <bool PERMUTE>
__global__ __launch_bounds__(256, 2)
void hmma_gemm_kernel(const unsigned* __restrict__ Ap, int ldaW,
                      const unsigned* __restrict__ Bp, int ldbW,
                      float* __restrict__ C, int ldc,
                      const float* __restrict__ bias, int K, int ncols)
{
    extern __shared__ unsigned char gsm[];
    unsigned* AS = (unsigned*)gsm;             // [3][128][HA_P]
    unsigned* BS = AS + H128_AS;               // [3][16][HB_P]

    const int tid = threadIdx.x;
    const int wid = tid >> 5, lane = tid & 31;
    const int wm = wid & 3, wn = wid >> 2;
    const int m0 = blockIdx.y * 128, n0 = blockIdx.x * 128;

    const int arow = tid >> 1, aw = (tid & 1) * 8;
    const int kp = tid >> 4, bc = (tid & 15) * 8;
    int colb = n0 + bc;
    if (colb > ncols - 8) colb = ncols - 8;

    float acc[2][8][4];
#pragma unroll
    for (int mi = 0; mi < 2; mi++)
#pragma unroll
        for (int ni = 0; ni < 8; ni++)
#pragma unroll
            for (int u = 0; u < 4; u++) acc[mi][ni][u] = 0.0f;

    auto stageA = [&](int p, int k0) {
        const unsigned* as = Ap + (size_t)(m0 + arow) * ldaW + (k0 >> 1) + aw;
        unsigned sm = (unsigned)__cvta_generic_to_shared(
            AS + p * (128 * HA_P) + arow * HA_P + aw);
        cpa16(sm, as); cpa16(sm + 16, as + 4);
        const unsigned* bs = Bp + (size_t)((k0 >> 1) + kp) * ldbW + colb;
        unsigned smb = (unsigned)__cvta_generic_to_shared(
            BS + p * (16 * HB_P) + kp * HB_P + bc);
        cpa16(smb, bs); cpa16(smb + 16, bs + 4);
    };
    auto compute = [&](int p) {
        const unsigned* A0 = AS + p * (128 * HA_P);
        const unsigned* B0 = BS + p * (16 * HB_P);
#pragma unroll
        for (int ks = 0; ks < 2; ks++) {
            unsigned af[2][4], bf[8][2];
#pragma unroll
            for (int mi = 0; mi < 2; mi++) {
                int r = wm * 32 + mi * 16 + (lane >> 2);
                af[mi][0] = A0[r * HA_P + ks * 8 + (lane & 3)];
                af[mi][1] = A0[(r + 8) * HA_P + ks * 8 + (lane & 3)];
                af[mi][2] = A0[r * HA_P + ks * 8 + (lane & 3) + 4];
                af[mi][3] = A0[(r + 8) * HA_P + ks * 8 + (lane & 3) + 4];
            }
#pragma unroll
            for (int ni = 0; ni < 8; ni++) {
                int c = wn * 64 + ni * 8 + (lane >> 2);
                bf[ni][0] = B0[(ks * 8 + (lane & 3)) * HB_P + c];
                bf[ni][1] = B0[(ks * 8 + (lane & 3) + 4) * HB_P + c];
            }
#pragma unroll
            for (int mi = 0; mi < 2; mi++)
#pragma unroll
                for (int ni = 0; ni < 8; ni++)
                    HMMA16(acc[mi][ni], af[mi], bf[ni]);
        }
    };

    stageA(0, 0);  CP_COMMIT();
    stageA(1, 32); CP_COMMIT();
    int buf = 0;
    for (int k0 = 64; k0 < K; k0 += 32) {
        CP_WAIT(1);
        __syncthreads();
        compute(buf);
        int nb = buf + 2; if (nb >= 3) nb -= 3;
        stageA(nb, k0); CP_COMMIT();
        buf = (buf == 2) ? 0 : buf + 1;
    }
    CP_WAIT(1); __syncthreads(); compute(buf);
    buf = (buf == 2) ? 0 : buf + 1;
    CP_WAIT(0); __syncthreads(); compute(buf);

#pragma unroll
    for (int mi = 0; mi < 2; mi++) {
        int r = m0 + wm * 32 + mi * 16 + (lane >> 2);
        int r0 = PERMUTE ? ((r & (B_ - 1)) * T_ + (r >> 4)) : r;
        int r8 = r + 8;
        int r1 = PERMUTE ? ((r8 & (B_ - 1)) * T_ + (r8 >> 4)) : r8;
#pragma unroll
        for (int ni = 0; ni < 8; ni++) {
            int c = n0 + wn * 64 + ni * 8 + (lane & 3) * 2;
            if (c < ncols) {
                float bc0 = bias[c], bc1 = bias[c + 1];
                C[(size_t)r0 * ldc + c]     = acc[mi][ni][0] + bc0;
                C[(size_t)r0 * ldc + c + 1] = acc[mi][ni][1] + bc1;
                C[(size_t)r1 * ldc + c]     = acc[mi][ni][2] + bc0;
                C[(size_t)r1 * ldc + c + 1] = acc[mi][ni][3] + bc1;
            }
        }
    }
}

// ---------------- fp16 GEMM, 256x128x32, 3-stage cp.async (vocab) -----------
__global__ __launch_bounds__(256, 1)
void hmma_gemm256_kernel(const unsigned* __restrict__ Ap, int ldaW,
                         const unsigned* __restrict__ Bp, int ldbW,
                         float* __restrict__ C, int ldc,
                         const float* __restrict__ bias, int K, int ncols)
{
    extern __shared__ unsigned char gsm[];
    unsigned* AS = (unsigned*)gsm;             // [3][256][HA_P]
    unsigned* BS = AS + H256_AS;               // [3][16][HB_P]

    const int tid = threadIdx.x;
    const int wid = tid >> 5, lane = tid & 31;
    const int wm = wid & 3, wn = wid >> 2;
    const int m0 = blockIdx.y * 256, n0 = blockIdx.x * 128;

    const int arow = tid >> 1, aw = (tid & 1) * 8;
    const int kp = tid >> 4, bc = (tid & 15) * 8;
    int colb = n0 + bc;
    if (colb > ncols - 8) colb = ncols - 8;

    float acc[4][8][4];
#pragma unroll
    for (int mi = 0; mi < 4; mi++)
#pragma unroll
        for (int ni = 0; ni < 8; ni++)
#pragma unroll
            for (int u = 0; u < 4; u++) acc[mi][ni][u] = 0.0f;

    auto stageA = [&](int p, int k0) {
#pragma unroll
        for (int h = 0; h < 2; h++) {
            const int r = arow + h * 128;
            const unsigned* as = Ap + (size_t)(m0 + r) * ldaW + (k0 >> 1) + aw;
            unsigned sm = (unsigned)__cvta_generic_to_shared(
                AS + p * (256 * HA_P) + r * HA_P + aw);
            cpa16(sm, as); cpa16(sm + 16, as + 4);
        }
        const unsigned* bs = Bp + (size_t)((k0 >> 1) + kp) * ldbW + colb;
        unsigned smb = (unsigned)__cvta_generic_to_shared(
            BS + p * (16 * HB_P) + kp * HB_P + bc);
        cpa16(smb, bs); cpa16(smb + 16, bs + 4);
    };
    auto compute = [&](int p) {
        const unsigned* A0 = AS + p * (256 * HA_P);
        const unsigned* B0 = BS + p * (16 * HB_P);
#pragma unroll
        for (int ks = 0; ks < 2; ks++) {
            unsigned af[4][4], bf[8][2];
#pragma unroll
            for (int mi = 0; mi < 4; mi++) {
                int r = wm * 64 + mi * 16 + (lane >> 2);
                af[mi][0] = A0[r * HA_P + ks * 8 + (lane & 3)];
                af[mi][1] = A0[(r + 8) * HA_P + ks * 8 + (lane & 3)];
                af[mi][2] = A0[r * HA_P + ks * 8 + (lane & 3) + 4];
                af[mi][3] = A0[(r + 8) * HA_P + ks * 8 + (lane & 3) + 4];
            }
#pragma unroll
            for (int ni = 0; ni < 8; ni++) {
                int c = wn * 64 + ni * 8 + (lane >> 2);
                bf[ni][0] = B0[(ks * 8 + (lane & 3)) * HB_P + c];
                bf[ni][1] = B0[(ks * 8 + (lane & 3) + 4) * HB_P + c];
            }
#pragma unroll
            for (int mi = 0; mi < 4; mi++)
#pragma unroll
                for (int ni = 0; ni < 8; ni++)
                    HMMA16(acc[mi][ni], af[mi], bf[ni]);
        }
    };

    stageA(0, 0);  CP_COMMIT();
    stageA(1, 32); CP_COMMIT();
    int buf = 0;
    for (int k0 = 64; k0 < K; k0 += 32) {
        CP_WAIT(1);
        __syncthreads();
        compute(buf);
        int nb = buf + 2; if (nb >= 3) nb -= 3;
        stageA(nb, k0); CP_COMMIT();
        buf = (buf == 2) ? 0 : buf + 1;
    }
    CP_WAIT(1); __syncthreads(); compute(buf);
    buf = (buf == 2) ? 0 : buf + 1;
    CP_WAIT(0); __syncthreads(); compute(buf);

#pragma unroll
    for (int mi = 0; mi < 4; mi++) {
        int r = m0 + wm * 64 + mi * 16 + (lane >> 2);
        int r0 = (r & (B_ - 1)) * T_ + (r >> 4);        // PERMUTE (vocab)
        int r8 = r + 8;
        int r1 = (r8 & (B_ - 1)) * T_ + (r8 >> 4);
#pragma unroll
        for (int ni = 0; ni < 8; ni++) {
            int c = n0 + wn * 64 + ni * 8 + (lane & 3) * 2;
            if (c < ncols) {
                float bc0 = bias[c], bc1 = bias[c + 1];
                C[(size_t)r0 * ldc + c]     = acc[mi][ni][0] + bc0;
                C[(size_t)r0 * ldc + c + 1] = acc[mi][ni][1] + bc1;
                C[(size_t)r1 * ldc + c]     = acc[mi][ni][2] + bc0;
                C[(size_t)r1 * ldc + c + 1] = acc[mi][ni][3] + bc1;
            }
        }
    }
}

// ---------------- grid-wide sense barrier (atomic; measured best) -----------
__device__ __forceinline__ void gsync(unsigned target) {
    __syncthreads();
    if (threadIdx.x == 0) {
        __threadfence();
        unsigned old = atomicAdd(&g_barcnt, 1);
        if (old == NBLK - 1) {
            g_barcnt = 0;
            __threadfence();
            g_barsense = target;
        } else {
            while (g_barsense < target) { __nanosleep(32); }
        }
        __threadfence();
    }
    __syncthreads();
}

// ---------------- persistent recurrence kernel (R11 verbatim) ---------------
__global__ __launch_bounds__(512, 1)
void recur_kernel(const float* __restrict__ Whh,
                  const float* __restrict__ Ws,
                  const float* __restrict__ bs,
                  const float* __restrict__ bhh)
{
    extern __shared__ unsigned char dsm[];
    unsigned* wt_all = (unsigned*)dsm;
    float*    hs     = (float*)(dsm + HS_OFF);
    unsigned (*sa)[136]     = (unsigned(*)[136])(dsm + SA_OFF);
    float    (*part)[16][66] = (float(*)[16][66])(dsm + PART_OFF);
    float    (*e_sh)[65]    = (float(*)[65])(dsm + E_OFF);
    float*    s2            = (float*)(dsm + SA_OFF);
    float    (*redp)[64]    = (float(*)[64])(dsm + SA_OFF + 2048);

    const int tid = threadIdx.x;
    const int bid = blockIdx.x;
    const int lane = tid & 31, wid = tid >> 5;

    const int q = bid & 7;
    const int gidx = bid >> 3;
    const int gcount = (q < 4) ? 19 : 18;
    const int c0t = gidx * 48 / gcount;
    const int c1t = (gidx + 1) * 48 / gcount;
    const int ntile = c1t - c0t;

    const int c0h = (G3_ * bid) / NBLK, c1h = (G3_ * (bid + 1)) / NBLK;
    const int ncolsh = c1h - c0h;

    for (int j = 0; j < ntile; j++) {
        const int c = c0t + j;
        const int rr = tid >> 4, c4 = (tid & 15) * 4;
        unsigned* wt = wt_all + j * WT_ELEMS;
#pragma unroll
        for (int p = 0; p < 4; p++) {
            int row = p * 32 + rr;
            float4 v = *reinterpret_cast<const float4*>(
                &Whh[(size_t)(q * 128 + row) * G3_ + c * 64 + c4]);
            wt[row * 72 + c4 + 0] = f2tf(v.x);
            wt[row * 72 + c4 + 1] = f2tf(v.y);
            wt[row * 72 + c4 + 2] = f2tf(v.z);
            wt[row * 72 + c4 + 3] = f2tf(v.w);
        }
    }
    for (int p = tid; p < 1024 * ncolsh; p += 512) {
        int row = p / ncolsh, cl = p - row * ncolsh;
        hs[cl * HSPITCH + row] = g_Hih[(size_t)row * G3_ + c0h + cl];
    }
    __syncthreads();

    const int half = wid >> 3;
    const int hwid = wid & 7;
    const int wk = hwid >> 2, wn = hwid & 3;

    unsigned bar = 0;
    for (int i = 0; i < T_; i++) {
        {
            const int b = tid >> 5, c4 = (tid & 31) * 4;
            float4 v = *reinterpret_cast<const float4*>(&g_s[b * H_ + q * 128 + c4]);
            sa[b][c4 + 0] = f2tf(v.x); sa[b][c4 + 1] = f2tf(v.y);
            sa[b][c4 + 2] = f2tf(v.z); sa[b][c4 + 3] = f2tf(v.w);
        }
        __syncthreads();
        for (int jj = 0; jj < ntile; jj += 2) {
            const int nt = (ntile - jj < 2) ? (ntile - jj) : 2;
            const int j = jj + half;
            float acc[2][4];
#pragma unroll
            for (int ni = 0; ni < 2; ni++)
#pragma unroll
                for (int u = 0; u < 4; u++) acc[ni][u] = 0.0f;
            if (half < nt) {
                const unsigned* wt = wt_all + j * WT_ELEMS;
#pragma unroll
                for (int k8 = 0; k8 < 8; k8++) {
                    const int kb = wk * 64 + k8 * 8;
                    unsigned af[4];
                    af[0] = sa[lane >> 2][kb + (lane & 3)];
                    af[1] = sa[(lane >> 2) + 8][kb + (lane & 3)];
                    af[2] = sa[lane >> 2][kb + (lane & 3) + 4];
                    af[3] = sa[(lane >> 2) + 8][kb + (lane & 3) + 4];
#pragma unroll
                    for (int ni = 0; ni < 2; ni++) {
                        const int cc = wn * 16 + ni * 8 + (lane >> 2);
                        unsigned bf0 = wt[(kb + (lane & 3)) * 72 + cc];
                        unsigned bf1 = wt[(kb + (lane & 3) + 4) * 72 + cc];
                        asm volatile(
                            "mma.sync.aligned.m16n8k8.row.col.f32.tf32.tf32.f32 "
                            "{%0,%1,%2,%3}, {%4,%5,%6,%7}, {%8,%9}, {%0,%1,%2,%3};"
                            : "+f"(acc[ni][0]), "+f"(acc[ni][1]),
                              "+f"(acc[ni][2]), "+f"(acc[ni][3])
                            : "r"(af[0]), "r"(af[1]), "r"(af[2]), "r"(af[3]),
                              "r"(bf0), "r"(bf1));
                    }
                }
            }
            __syncthreads();
            if (half < nt && wk == 1) {
#pragma unroll
                for (int ni = 0; ni < 2; ni++) {
                    const int r = lane >> 2, cc = wn * 16 + ni * 8 + (lane & 3) * 2;
                    part[half][r][cc]         = acc[ni][0];
                    part[half][r][cc + 1]     = acc[ni][1];
                    part[half][r + 8][cc]     = acc[ni][2];
                    part[half][r + 8][cc + 1] = acc[ni][3];
                }
            }
            __syncthreads();
            if (half < nt && wk == 0) {
                const int c = c0t + j;
#pragma unroll
                for (int ni = 0; ni < 2; ni++) {
                    const int r = lane >> 2, cc = wn * 16 + ni * 8 + (lane & 3) * 2;
                    const int gc = c * 64 + cc;
                    g_gpart[(size_t)(q * 16 + r) * G3_ + gc] =
                        acc[ni][0] + part[half][r][cc];
                    g_gpart[(size_t)(q * 16 + r) * G3_ + gc + 1] =
                        acc[ni][1] + part[half][r][cc + 1];
                    g_gpart[(size_t)(q * 16 + r + 8) * G3_ + gc] =
                        acc[ni][2] + part[half][r + 8][cc];
                    g_gpart[(size_t)(q * 16 + r + 8) * G3_ + gc + 1] =
                        acc[ni][3] + part[half][r + 8][cc + 1];
                }
            }
            __syncthreads();
        }
        if (tid < 256) {
            const int b2 = (tid >> 5) * 2 + (lane >> 4);
            const int j0 = (lane & 15) * 4;
            float a[4];
#pragma unroll
            for (int u = 0; u < 4; u++) {
                int jx = j0 + u;
                float v = bs[jx] + g_hemb[(b2 * T_ + i) * T_ + jx];
#pragma unroll
                for (int kc = 0; kc < 2; kc++) v += g_alignpart[kc][b2][jx];
                a[u] = tanhf(v);
            }
            float m = fmaxf(fmaxf(a[0], a[1]), fmaxf(a[2], a[3]));
#pragma unroll
            for (int o = 8; o > 0; o >>= 1)
                m = fmaxf(m, __shfl_xor_sync(0xffffffffu, m, o));
            float ex[4], ssum = 0.0f;
#pragma unroll
            for (int u = 0; u < 4; u++) { ex[u] = __expf(a[u] - m); ssum += ex[u]; }
#pragma unroll
            for (int o = 8; o > 0; o >>= 1)
                ssum += __shfl_xor_sync(0xffffffffu, ssum, o);
            float inv = 1.0f / ssum;
#pragma unroll
            for (int u = 0; u < 4; u++) {
                e_sh[b2][j0 + u] = ex[u] * inv;
                if (bid == 0) g_E[(i * B_ + b2) * T_ + j0 + u] = ex[u] * inv;
            }
        }
        __syncthreads();
        for (int p = tid; p < 16 * ncolsh; p += 512) {
            const int b = p / ncolsh, cl = p - b * ncolsh;
            const float* hrow = hs + cl * HSPITCH + b * 64;
            float a0 = 0.0f, a1 = 0.0f;
#pragma unroll
            for (int t = 0; t < 64; t += 4) {
                float2 h0 = *reinterpret_cast<const float2*>(hrow + t);
                float2 h1 = *reinterpret_cast<const float2*>(hrow + t + 2);
                a0 += e_sh[b][t] * h0.x + e_sh[b][t + 1] * h0.y;
                a1 += e_sh[b][t + 2] * h1.x + e_sh[b][t + 3] * h1.y;
            }
            g_gpart[(size_t)(8 * 16 + b) * G3_ + c0h + cl] = a0 + a1;
        }
        gsync(++bar);
        if (bid < 32) {
            const int b = bid >> 1, hf = bid & 1;
            const int k = hf * 512 + tid;

            float gr = bhh[k], gz = bhh[H_ + k], hn = bhh[2 * H_ + k];
#pragma unroll
            for (int qq = 0; qq < 8; qq++) {
                const float* P = g_gpart + (size_t)(qq * 16 + b) * G3_;
                gr += P[k]; gz += P[H_ + k]; hn += P[2 * H_ + k];
            }
            const float* P8 = g_gpart + (size_t)(8 * 16 + b) * G3_;
            gr += P8[k]; gz += P8[H_ + k];
            float inn = P8[2 * H_ + k];

            float r = 1.0f / (1.0f + __expf(-gr));
            float z = 1.0f / (1.0f + __expf(-gz));
            float n = tanhf(inn + r * hn);
            float sold = g_s[b * H_ + k];
            float snew = (1.0f - z) * n + z * sold;
            g_s[b * H_ + k] = snew;
            g_cat[(size_t)(i * B_ + b) * CAT_ + k] = snew;

            s2[tid] = snew;
            __syncthreads();
            const int j = tid & 63, sub = tid >> 6;
            float a = 0.0f;
#pragma unroll 8
            for (int kk = 0; kk < 64; kk++)
                a += s2[sub * 64 + kk] *
                     Ws[(size_t)(hf * 512 + sub * 64 + kk) * T_ + j];
            redp[sub][j] = a;
            __syncthreads();
            if (tid < 64)
                g_alignpart[hf][b][tid] =
                    redp[0][tid] + redp[1][tid] + redp[2][tid] + redp[3][tid] +
                    redp[4][tid] + redp[5][tid] + redp[6][tid] + redp[7][tid];
        }
        gsync(++bar);
    }
}

// ---------------- batched context -------------------------------------------
__global__ __launch_bounds__(128)
void ctx_kernel(const float* __restrict__ h)
{
    const int b = blockIdx.x, dc = blockIdx.y, tid = threadIdx.x;
    __shared__ float sh_h[T_][128];
    __shared__ float e_sh[T_];
    const int dbase = dc * 128;
    for (int t = 0; t < T_; t++)
        sh_h[t][tid] = h[(size_t)(b * T_ + t) * D_ + dbase + tid];
    __syncthreads();
    for (int i = 0; i < T_; i++) {
        if (tid < 64) e_sh[tid] = g_E[(i * B_ + b) * T_ + tid];
        __syncthreads();
        float acc = 0.0f;
#pragma unroll 8
        for (int t = 0; t < T_; t++) acc += e_sh[t] * sh_h[t][tid];
        g_cat[(size_t)(i * B_ + b) * CAT_ + H_ + EMB_ + dbase + tid] = acc;
        __syncthreads();
    }
}

// ---------------- maxout -> packed half2 ------------------------------------
__global__ void maxout_kernel()
{
    const int idx = blockIdx.x * blockDim.x + threadIdx.x;   // word index
    const int r = idx >> 9, m2 = idx & 511;
    const float* row = g_tt + (size_t)r * (2 * MO_);
    float a = fmaxf(row[2 * m2],     row[MO_ + 2 * m2]);
    float b = fmaxf(row[2 * m2 + 1], row[MO_ + 2 * m2 + 1]);
    g_tmaxh[idx] = f2h2(a, b);
}

// ---------------------------------------------------------------------------
extern "C" void kernel_launch(void* const* d_in, const int* in_sizes, int n_in,
                              void* d_out, int out_size)
{
    (void)in_sizes; (void)n_in; (void)out_size;
    const float* h     = (const float*)d_in[0];
    const float* W_h   = (const float*)d_in[1];
    const float* b_h   = (const float*)d_in[2];
    const float* W_s   = (const float*)d_in[3];
    const float* b_s   = (const float*)d_in[4];
    const float* W_ih  = (const float*)d_in[5];
    const float* b_ih  = (const float*)d_in[6];
    const float* W_hh  = (const float*)d_in[7];
    const float* b_hh  = (const float*)d_in[8];
    const float* W_emb = (const float*)d_in[9];
    const float* b_emb = (const float*)d_in[10];
    const float* W_t   = (const float*)d_in[11];
    const float* b_t   = (const float*)d_in[12];
    const float* W_out = (const float*)d_in[13];
    const float* b_out = (const float*)d_in[14];
    float* out = (float*)d_out;

    float *p_hemb, *p_Hih, *p_cat, *p_tt;
    unsigned *p_hp, *p_Whp, *p_Wihp, *p_Wembp, *p_Wtp, *p_Woutp, *p_cath, *p_tmaxh;
    cudaGetSymbolAddress((void**)&p_hemb, g_hemb);
    cudaGetSymbolAddress((void**)&p_Hih,  g_Hih);
    cudaGetSymbolAddress((void**)&p_cat,  g_cat);
    cudaGetSymbolAddress((void**)&p_tt,   g_tt);
    cudaGetSymbolAddress((void**)&p_hp,   g_h_p);
    cudaGetSymbolAddress((void**)&p_Whp,  g_Wh_p);
    cudaGetSymbolAddress((void**)&p_Wihp, g_Wih_p);
    cudaGetSymbolAddress((void**)&p_Wembp, g_Wemb_p);
    cudaGetSymbolAddress((void**)&p_Wtp,  g_Wt_p);
    cudaGetSymbolAddress((void**)&p_Woutp, g_Wout_p);
    cudaGetSymbolAddress((void**)&p_cath, g_cath);
    cudaGetSymbolAddress((void**)&p_tmaxh, g_tmaxh);

    static int smem_set = 0;
    if (!smem_set) {
        cudaFuncSetAttribute(recur_kernel,
            cudaFuncAttributeMaxDynamicSharedMemorySize, DSMEM_BYTES);
        cudaFuncSetAttribute(hmma_gemm_kernel<false>,
            cudaFuncAttributeMaxDynamicSharedMemorySize, H128_SMEM);
        cudaFuncSetAttribute(hmma_gemm256_kernel,
            cudaFuncAttributeMaxDynamicSharedMemorySize, H256_SMEM);
        smem_set = 1;
    }

    init_kernel<<<(B_ * H_ + 255) / 256, 256>>>();

    // ---- packs (weights + h) ----
    pack_rows_kernel<<<(B_ * T_ * (D_ / 2) + 255) / 256, 256>>>(
        h, p_hp, B_ * T_, D_ / 2, D_, D_ / 2);
    pack_b_kernel<<<((D_ / 2) * T_ + 255) / 256, 256>>>(W_h, p_Whp, D_ / 2, T_);
    pack_b_kernel<<<((D_ / 2) * G3_ + 255) / 256, 256>>>(W_ih, p_Wihp, D_ / 2, G3_);
    pack_b_kernel<<<((H_ / 2) * EMB_ + 255) / 256, 256>>>(W_emb, p_Wembp, H_ / 2, EMB_);
    pack_b_kernel<<<((CAT_ / 2) * 2 * MO_ + 255) / 256, 256>>>(W_t, p_Wtp, CAT_ / 2, 2 * MO_);
    pack_b_kernel<<<((MO_ / 2) * V_ + 255) / 256, 256>>>(W_out, p_Woutp, MO_ / 2, V_);

    // ---- precompute: hemb (fp32 out), Hih (fp32 out) ----
    hmma_gemm_kernel<false><<<dim3(1, (B_ * T_) / 128), 256, H128_SMEM>>>(
        p_hp, D_ / 2, p_Whp, T_, p_hemb, T_, b_h, D_, T_);
    hmma_gemm_kernel<false><<<dim3(G3_ / 128, (B_ * T_) / 128), 256, H128_SMEM>>>(
        p_hp, D_ / 2, p_Wihp, G3_, p_Hih, G3_, b_ih, D_, G3_);

    // ---- persistent recurrence ----
    recur_kernel<<<NBLK, 512, DSMEM_BYTES>>>(W_hh, W_s, b_s, b_hh);

    // ---- epilogue ----
    ctx_kernel<<<dim3(B_, D_ / 128), 128>>>(h);
    // pack s-part of cat, run y_emb, pack rest, t_tilde, maxout, vocab
    pack_rows_kernel<<<(T_ * B_ * (H_ / 2) + 255) / 256, 256>>>(
        p_cat, p_cath, T_ * B_, H_ / 2, CAT_, CAT_ / 2);
    hmma_gemm_kernel<false><<<dim3(EMB_ / 128, (T_ * B_) / 128), 256, H128_SMEM>>>(
        p_cath, CAT_ / 2, p_Wembp, EMB_, p_cat + H_, CAT_, b_emb, H_, EMB_);
    pack_rows_kernel<<<(T_ * B_ * ((EMB_ + D_) / 2) + 255) / 256, 256>>>(
        p_cat + H_, p_cath + H_ / 2, T_ * B_, (EMB_ + D_) / 2, CAT_, CAT_ / 2);
    hmma_gemm_kernel<false><<<dim3(2 * MO_ / 128, (T_ * B_) / 128), 256, H128_SMEM>>>(
        p_cath, CAT_ / 2, p_Wtp, 2 * MO_, p_tt, 2 * MO_, b_t, CAT_, 2 * MO_);
    maxout_kernel<<<(T_ * B_ * (MO_ / 2)) / 256, 256>>>();
    hmma_gemm256_kernel<<<dim3(V_ / 128, (T_ * B_) / 256), 256, H256_SMEM>>>(
        p_tmaxh, MO_ / 2, p_Woutp, V_, out, V_, b_out, MO_, V_);
}